// round 13
// baseline (speedup 1.0000x reference)
#include <cuda_runtime.h>
#include <cuda_bf16.h>
#include <math.h>
#include <string.h>

typedef unsigned int u32;
typedef unsigned long long u64;

// ---------------------------------------------------------------------------
// Problem constants
// ---------------------------------------------------------------------------
constexpr int T    = 64;
constexpr int B    = 2048;
constexpr int H    = 256;
constexpr int H1   = 64;
constexpr int H2   = 64;
constexpr int OUTD = 601;
constexpr int RROWS = 64;
constexpr int NTILE = T * B / RROWS;      // 2048 MLP tiles
constexpr int NCOPY = 8;                  // h_last copy tiles (256 rows each)
constexpr int NTILE_TOT = NTILE + NCOPY;  // 2056

// ---------------------------------------------------------------------------
// PTX helpers
// ---------------------------------------------------------------------------
__device__ __forceinline__ u32 smem_u32(const void* p) {
    u32 a;
    asm("{ .reg .u64 t; cvta.to.shared.u64 t, %1; cvt.u32.u64 %0, t; }"
        : "=r"(a) : "l"(p));
    return a;
}
__device__ __forceinline__ void ldsm_x4(u32& r0, u32& r1, u32& r2, u32& r3, u32 addr) {
    asm volatile("ldmatrix.sync.aligned.m8n8.x4.shared.b16 {%0,%1,%2,%3}, [%4];"
                 : "=r"(r0), "=r"(r1), "=r"(r2), "=r"(r3) : "r"(addr));
}
__device__ __forceinline__ void mma_bf16(float* d, const u32* a, const u32* b) {
    asm volatile(
        "mma.sync.aligned.m16n8k16.row.col.f32.bf16.bf16.f32 "
        "{%0,%1,%2,%3}, {%4,%5,%6,%7}, {%8,%9}, {%0,%1,%2,%3};"
        : "+f"(d[0]), "+f"(d[1]), "+f"(d[2]), "+f"(d[3])
        : "r"(a[0]), "r"(a[1]), "r"(a[2]), "r"(a[3]), "r"(b[0]), "r"(b[1]));
}
__device__ __forceinline__ void cp16(u32 dst, const void* src) {
    asm volatile("cp.async.ca.shared.global [%0], [%1], 16;" :: "r"(dst), "l"(src));
}
__device__ __forceinline__ void cp_commit() {
    asm volatile("cp.async.commit_group;" ::: "memory");
}
template <int N>
__device__ __forceinline__ void cp_wait_group() {
    asm volatile("cp.async.wait_group %0;" :: "n"(N) : "memory");
}
__device__ __forceinline__ u32 bf2u(__nv_bfloat162 v) {
    u32 r; memcpy(&r, &v, 4); return r;
}
__device__ __forceinline__ float2 u2f2(u32 v) {
    __nv_bfloat162 b; memcpy(&b, &v, 4);
    return make_float2(__bfloat162float(b.x), __bfloat162float(b.y));
}
__device__ __forceinline__ u64 ffma2(u64 a, u64 b, u64 c) {
    u64 d; asm("fma.rn.f32x2 %0, %1, %2, %3;" : "=l"(d) : "l"(a), "l"(b), "l"(c));
    return d;
}
__device__ __forceinline__ u64 pack2(float x, float y) {
    u64 d; asm("mov.b64 %0, {%1, %2};" : "=l"(d) : "f"(x), "f"(y));
    return d;
}
__device__ __forceinline__ float2 unpack2(u64 v) {
    float2 r; asm("mov.b64 {%0, %1}, %2;" : "=f"(r.x), "=f"(r.y) : "l"(v));
    return r;
}
constexpr float LOG2E = 1.4426950408889634f;
__device__ __forceinline__ float fast_sigmoid(float v) {
    float e; asm("ex2.approx.f32 %0, %1;" : "=f"(e) : "f"(-LOG2E * v));
    float r; asm("rcp.approx.f32 %0, %1;" : "=f"(r) : "f"(1.f + e));
    return r;
}
__device__ __forceinline__ float fast_tanh(float v) {
    float e; asm("ex2.approx.f32 %0, %1;" : "=f"(e) : "f"(2.f * LOG2E * v));
    float r; asm("rcp.approx.f32 %0, %1;" : "=f"(r) : "f"(1.f + e));
    return 1.f - 2.f * r;
}
__device__ __forceinline__ float fast_elu(float v) {
    if (v > 0.f) return v;
    float e; asm("ex2.approx.f32 %0, %1;" : "=f"(e) : "f"(LOG2E * v));
    return e - 1.f;
}

// ---------------------------------------------------------------------------
// Device scratch
// ---------------------------------------------------------------------------
__device__ u32 g_hhi[(size_t)T * B * (H / 2)];   // [t][b][kp] bf16x2 hi
__device__ u32 g_hlo[(size_t)T * B * (H / 2)];   // [t][b][kp] bf16x2 lo
// w_hh pre-split + permuted for cp16 streaming:
// [chunk c 0..7][prow 0..767][u32 0..15 = hi k-pairs][u32 16..31 = lo k-pairs]
// prow = wn*48 + g*16 + jj  (wn = j-group 0..15, g = gate, jj = j within group)
__device__ u32 g_wsp[(size_t)8 * 768 * 32];
__device__ u32 g_cnt[64 * 32] = {};  // per-block (32 rows) monotonic counters
__device__ u32 g_q = 0;              // work queue

// ---------------------------------------------------------------------------
// Weight split + permute prep
// ---------------------------------------------------------------------------
__global__ void prep_w_kernel(const float* __restrict__ w_hh)
{
    int i = blockIdx.x * blockDim.x + threadIdx.x;   // 8*768*16 = 98304
    if (i >= 8 * 768 * 16) return;
    int c    = i / 12288;
    int rem  = i % 12288;
    int prow = rem >> 4;
    int u    = rem & 15;
    int wn = prow / 48;
    int r2 = prow % 48;
    int g  = r2 >> 4;
    int jj = r2 & 15;
    int orow = g * 256 + wn * 16 + jj;
    int k = c * 32 + u * 2;
    float2 w = *(const float2*)&w_hh[(size_t)orow * H + k];
    __nv_bfloat162 hi = __floats2bfloat162_rn(w.x, w.y);
    __nv_bfloat162 lo = __floats2bfloat162_rn(w.x - __bfloat162float(hi.x),
                                              w.y - __bfloat162float(hi.y));
    size_t base = ((size_t)c * 768 + prow) * 32;
    g_wsp[base + u]      = bf2u(hi);
    g_wsp[base + 16 + u] = bf2u(lo);
}

// ---------------------------------------------------------------------------
// Fused persistent kernel: 148 blocks x 512 threads.
// Blocks 0..63: block-LOCAL GRU (32 batches x full H). No inter-block sync.
//   A (h, bf16 hi/lo) resident in smem; W streamed from L2 in 8 k-chunks
//   (2-buffer cp.async ring). 16 MMA warps, warp tile M32 x N48.
// Blocks 64..147: MLP consumers from t=0. GRU blocks join after recurrence.
// ---------------------------------------------------------------------------
constexpr int GRID_P = 148;
constexpr int NGRU   = 64;
constexpr int SM_W   = 0;          // 2 bufs x 98304 (768 rows x 128B swizzled)
constexpr int SM_A   = 196608;     // 8 chunks x (32 rows x 128B) = 32768
constexpr int SM_Q   = 229376;     // queue slot
constexpr int FUSED_SMEM = 229504;

__global__ void __launch_bounds__(512, 1)
fused_persist(const float* __restrict__ h0,
              const float* __restrict__ x,
              const float* __restrict__ w_ih,
              const float* __restrict__ b_ih,
              const float* __restrict__ b_hh,
              const float* __restrict__ w1, const float* __restrict__ b1,
              const float* __restrict__ w2, const float* __restrict__ b2,
              const float* __restrict__ w3, const float* __restrict__ b3,
              float* __restrict__ out)
{
    extern __shared__ char smem[];
    const u32 sb = smem_u32(smem);
    const int tid  = threadIdx.x;

    // =====================================================================
    // GRU producer part (blocks 0..63), fully block-local recurrence
    // =====================================================================
    if (blockIdx.x < NGRU) {
        const int wid  = tid >> 5;       // warp = j-group wn (0..15)
        const int lane = tid & 31;
        const int bg = blockIdx.x;
        const int b0 = bg * 32;
        const int wn = wid;
        const int l4 = lane >> 2;
        const int lp = lane & 3;

        const int a_row = lane & 15;
        const int a_ch  = lane >> 4;            // A k16-half cell
        const int b_row = ((lane >> 4) << 3) + (lane & 7);
        const int b_ch  = (lane >> 3) & 1;      // W k16-half cell

        // gate params in registers: 4 j-values per lane
        float prm[2][2][7];   // [sub][e][param]
        #pragma unroll
        for (int sub = 0; sub < 2; sub++)
            #pragma unroll
            for (int e = 0; e < 2; e++) {
                int j = wn * 16 + sub * 8 + 2 * lp + e;
                prm[sub][e][0] = w_ih[j];
                prm[sub][e][1] = w_ih[H + j];
                prm[sub][e][2] = w_ih[2 * H + j];
                prm[sub][e][3] = b_ih[j]         + b_hh[j];
                prm[sub][e][4] = b_ih[H + j]     + b_hh[H + j];
                prm[sub][e][5] = b_ih[2 * H + j];
                prm[sub][e][6] = b_hh[2 * H + j];
            }

        // register-resident h state: rows mt*16+half*8+l4, j pairs per sub
        float2 hst[4][2];
        #pragma unroll
        for (int e = 0; e < 4; e++)
            #pragma unroll
            for (int sub = 0; sub < 2; sub++) {
                int rowg = b0 + (e >> 1) * 16 + (e & 1) * 8 + l4;
                int jl = wn * 16 + sub * 8 + 2 * lp;
                hst[e][sub] = *(const float2*)&h0[(size_t)rowg * H + jl];
            }

        // stage A (h0) resident: 8 chunks x [32 rows][128B swizzled hi|lo]
        #pragma unroll
        for (int i = 0; i < 8; i++) {
            int f = tid + i * 512;           // 4096 = 32 rows x 128 kp
            int row = f >> 7, kp = f & 127;
            float2 hv = *(const float2*)&h0[(size_t)(b0 + row) * H + 2 * kp];
            __nv_bfloat162 h2 = __floats2bfloat162_rn(hv.x, hv.y);
            __nv_bfloat162 l2 = __floats2bfloat162_rn(hv.x - __bfloat162float(h2.x),
                                                      hv.y - __bfloat162float(h2.y));
            int s = kp >> 4;
            int ch = (kp & 15) >> 2;
            u32 base = (u32)(s * 4096 + row * 128) + (u32)((kp & 3) * 4);
            *(u32*)(smem + SM_A + base + ((ch ^ (row & 7)) << 4))       = bf2u(h2);
            *(u32*)(smem + SM_A + base + (((ch + 4) ^ (row & 7)) << 4)) = bf2u(l2);
        }
        __syncthreads();

        for (int t = 0; t < T; t++) {
            // x for this lane's 4 rows
            float xvv[4];
            #pragma unroll
            for (int e = 0; e < 4; e++)
                xvv[e] = x[(size_t)t * B + b0 + (e >> 1) * 16 + (e & 1) * 8 + l4];

            float acc[2][3][2][4];
            #pragma unroll
            for (int mt = 0; mt < 2; mt++)
                #pragma unroll
                for (int g = 0; g < 3; g++)
                    #pragma unroll
                    for (int s = 0; s < 2; s++)
                        #pragma unroll
                        for (int q = 0; q < 4; q++) acc[mt][g][s][q] = 0.f;

            // stage W chunk 0 into buf0
            #pragma unroll
            for (int i = 0; i < 12; i++) {
                int f = tid + i * 512;       // 6144 = 768 rows x 8 cells
                int rr = f >> 3, cl = f & 7;
                cp16(sb + SM_W + rr * 128 + ((cl ^ (rr & 7)) << 4),
                     (const char*)g_wsp + (size_t)rr * 128 + cl * 16);
            }
            cp_commit();

            for (int c = 0; c < 8; c++) {
                cp_wait_group<0>();
                __syncthreads();     // chunk c staged by all; prev buf free
                if (c < 7) {
                    u32 wbn = sb + SM_W + ((c + 1) & 1) * 98304;
                    #pragma unroll
                    for (int i = 0; i < 12; i++) {
                        int f = tid + i * 512;
                        int rr = f >> 3, cl = f & 7;
                        cp16(wbn + rr * 128 + ((cl ^ (rr & 7)) << 4),
                             (const char*)g_wsp + ((size_t)(c + 1) * 768 + rr) * 128
                                                + cl * 16);
                    }
                    cp_commit();
                }

                const u32 wb  = sb + SM_W + (c & 1) * 98304;
                const u32 abc = sb + SM_A + c * 4096;
                #pragma unroll
                for (int ks = 0; ks < 2; ks++) {
                    u32 ahi[2][4], alo[2][4];
                    #pragma unroll
                    for (int mt = 0; mt < 2; mt++) {
                        int r = mt * 16 + a_row;
                        u32 bb = abc + (u32)(r * 128);
                        ldsm_x4(ahi[mt][0], ahi[mt][1], ahi[mt][2], ahi[mt][3],
                                bb + (u32)(((ks * 2 + a_ch) ^ (r & 7)) << 4));
                        ldsm_x4(alo[mt][0], alo[mt][1], alo[mt][2], alo[mt][3],
                                bb + (u32)(((ks * 2 + a_ch + 4) ^ (r & 7)) << 4));
                    }
                    #pragma unroll
                    for (int g = 0; g < 3; g++) {
                        int rr = wn * 48 + g * 16 + b_row;
                        u32 bb = wb + (u32)(rr * 128);
                        u32 bh[4], bl[4];
                        ldsm_x4(bh[0], bh[1], bh[2], bh[3],
                                bb + (u32)(((ks * 2 + b_ch) ^ (rr & 7)) << 4));
                        ldsm_x4(bl[0], bl[1], bl[2], bl[3],
                                bb + (u32)(((ks * 2 + b_ch + 4) ^ (rr & 7)) << 4));
                        #pragma unroll
                        for (int mt = 0; mt < 2; mt++) {
                            mma_bf16(acc[mt][g][0], ahi[mt], bh);       // hi*whi
                            mma_bf16(acc[mt][g][1], ahi[mt], bh + 2);
                            mma_bf16(acc[mt][g][0], ahi[mt], bl);       // hi*wlo
                            mma_bf16(acc[mt][g][1], ahi[mt], bl + 2);
                            mma_bf16(acc[mt][g][0], alo[mt], bh);       // lo*whi
                            mma_bf16(acc[mt][g][1], alo[mt], bh + 2);
                        }
                    }
                }
            }
            __syncthreads();   // all warps done reading A before epilogue rewrites

            // ---- epilogue: gates, update h regs, write A smem + global bf16 ----
            #pragma unroll
            for (int mt = 0; mt < 2; mt++)
                #pragma unroll
                for (int half = 0; half < 2; half++) {
                    int e = mt * 2 + half;
                    int rowl = mt * 16 + half * 8 + l4;
                    int rowg = b0 + rowl;
                    float xv = xvv[e];
                    #pragma unroll
                    for (int sub = 0; sub < 2; sub++) {
                        float hn0, hn1;
                        {
                            const float* P = prm[sub][0];
                            float r = fast_sigmoid(xv * P[0] + P[3]
                                                   + acc[mt][0][sub][half * 2]);
                            float z = fast_sigmoid(xv * P[1] + P[4]
                                                   + acc[mt][1][sub][half * 2]);
                            float n = fast_tanh(xv * P[2] + P[5]
                                                + r * (acc[mt][2][sub][half * 2] + P[6]));
                            hn0 = (1.f - z) * n + z * hst[e][sub].x;
                        }
                        {
                            const float* P = prm[sub][1];
                            float r = fast_sigmoid(xv * P[0] + P[3]
                                                   + acc[mt][0][sub][half * 2 + 1]);
                            float z = fast_sigmoid(xv * P[1] + P[4]
                                                   + acc[mt][1][sub][half * 2 + 1]);
                            float n = fast_tanh(xv * P[2] + P[5]
                                                + r * (acc[mt][2][sub][half * 2 + 1] + P[6]));
                            hn1 = (1.f - z) * n + z * hst[e][sub].y;
                        }
                        hst[e][sub] = make_float2(hn0, hn1);

                        __nv_bfloat162 h2 = __floats2bfloat162_rn(hn0, hn1);
                        __nv_bfloat162 l2 = __floats2bfloat162_rn(
                            hn0 - __bfloat162float(h2.x),
                            hn1 - __bfloat162float(h2.y));
                        u32 uhi = bf2u(h2), ulo = bf2u(l2);

                        int kp = wn * 8 + sub * 4 + lp;
                        g_hhi[((size_t)t * B + rowg) * 128 + kp] = uhi;
                        g_hlo[((size_t)t * B + rowg) * 128 + kp] = ulo;

                        int s  = kp >> 4;
                        int ch = (kp & 15) >> 2;
                        u32 base = (u32)(s * 4096 + rowl * 128) + (u32)((kp & 3) * 4);
                        *(u32*)(smem + SM_A + base + ((ch ^ (rowl & 7)) << 4))       = uhi;
                        *(u32*)(smem + SM_A + base + (((ch + 4) ^ (rowl & 7)) << 4)) = ulo;
                    }
                }

            // release h_t to MLP consumers; also orders A writes for next step
            __threadfence();
            __syncthreads();
            if (tid == 0) atomicAdd(&g_cnt[bg * 32], 1u);
        }
        __syncthreads();
    }

    // =====================================================================
    // Consumer part (all blocks): MLP tiles + h_last copy tiles
    // =====================================================================
    {
        float* sm  = (float*)smem;
        float* xt  = sm;            // [64][256]
        float* w1s = sm + 16384;    // [64][260]
        float* h1s = sm + 33024;    // [64][64]
        float* h2t = sm + 37120;    // [64][66]
        float* w3s = sm;            // alias xt
        float* w2s = sm + 16384;    // alias w1s
        u32* qs = (u32*)(smem + SM_Q);

        const int jp = tid & 31;
        const int rg = (tid >> 5) & 7;
        const bool act = tid < 256;

        for (;;) {
            __syncthreads();
            if (tid == 0) *qs = atomicAdd(&g_q, 1u);
            __syncthreads();
            u32 q = *qs;
            if (q >= (u32)NTILE_TOT) {
                if (q == (u32)(NTILE_TOT + GRID_P - 1) && tid == 0) {
                    for (int i = 0; i < 64; i++) g_cnt[i * 32] = 0;
                    __threadfence();
                    atomicExch(&g_q, 0u);
                }
                break;
            }

            if (q >= (u32)NTILE) {
                // h_last copy tile: rows seg*256..+256 -> producers seg*8..+8
                int seg = (int)(q - NTILE);
                if (tid < 8) {
                    u32 g;
                    do {
                        asm volatile("ld.acquire.gpu.global.u32 %0, [%1];"
                                     : "=r"(g) : "l"(&g_cnt[(seg * 8 + tid) * 32]));
                    } while ((int)(g - (u32)T) < 0);
                }
                __syncthreads();
                size_t base = ((size_t)(T - 1) * B + (size_t)seg * 256) * 128;
                float* dst = out + (size_t)T * B * OUTD + (size_t)seg * 256 * H;
                for (int i = tid; i < 256 * 128; i += 512) {
                    float2 a = u2f2(g_hhi[base + i]);
                    float2 b = u2f2(g_hlo[base + i]);
                    *(float2*)&dst[2 * i] = make_float2(a.x + b.x, a.y + b.y);
                }
                continue;
            }

            int tt = (int)(q >> 5);
            int tb = (int)(q & 31);   // producers 2tb, 2tb+1

            if (tid < 2) {
                u32 target = (u32)(tt + 1), g;
                do {
                    asm volatile("ld.acquire.gpu.global.u32 %0, [%1];"
                                 : "=r"(g) : "l"(&g_cnt[(2 * tb + tid) * 32]));
                } while ((int)(g - target) < 0);
            }
            __syncthreads();

            const size_t row0 = (size_t)q * RROWS;

            // reconstruct xt fp32 from bf16 hi/lo
            {
                const u32* hh = g_hhi + row0 * 128;
                const u32* ll = g_hlo + row0 * 128;
                for (int i = tid; i < RROWS * 128; i += 512) {
                    float2 a = u2f2(hh[i]);
                    float2 b = u2f2(ll[i]);
                    int row = i >> 7, kp = i & 127;
                    *(float2*)&xt[row * 256 + 2 * kp] = make_float2(a.x + b.x, a.y + b.y);
                }
            }
            for (int f = tid; f < H * H1; f += 512) {
                int jj = f & 63; int k = f >> 6;
                w1s[jj * 260 + k] = w1[f];
            }
            __syncthreads();

            // Stage 1
            if (act) {
                float acc[8][2];
                #pragma unroll
                for (int i = 0; i < 8; i++) { acc[i][0] = 0.f; acc[i][1] = 0.f; }
                #pragma unroll 4
                for (int k = 0; k < H; k += 4) {
                    float4 wa = *(const float4*)&w1s[(2 * jp) * 260 + k];
                    float4 wb = *(const float4*)&w1s[(2 * jp + 1) * 260 + k];
                    #pragma unroll
                    for (int i = 0; i < 8; i++) {
                        float4 xv = *(const float4*)&xt[(rg * 8 + i) * H + k];
                        acc[i][0] += xv.x * wa.x + xv.y * wa.y + xv.z * wa.z + xv.w * wa.w;
                        acc[i][1] += xv.x * wb.x + xv.y * wb.y + xv.z * wb.z + xv.w * wb.w;
                    }
                }
                float ba = b1[2 * jp], bb = b1[2 * jp + 1];
                #pragma unroll
                for (int i = 0; i < 8; i++) {
                    h1s[(rg * 8 + i) * 64 + 2 * jp]     = fast_elu(acc[i][0] + ba);
                    h1s[(rg * 8 + i) * 64 + 2 * jp + 1] = fast_elu(acc[i][1] + bb);
                }
            }
            __syncthreads();

            for (int f = tid; f < H1 * H2; f += 512) {
                int jj = f & 63; int k = f >> 6;
                w2s[jj * 68 + k] = w2[f];
            }
            __syncthreads();

            // Stage 2 (h2 transposed)
            if (act) {
                float acc[8][2];
                #pragma unroll
                for (int i = 0; i < 8; i++) { acc[i][0] = 0.f; acc[i][1] = 0.f; }
                #pragma unroll
                for (int k = 0; k < H1; k += 4) {
                    float4 wa = *(const float4*)&w2s[(2 * jp) * 68 + k];
                    float4 wb = *(const float4*)&w2s[(2 * jp + 1) * 68 + k];
                    #pragma unroll
                    for (int i = 0; i < 8; i++) {
                        float4 xv = *(const float4*)&h1s[(rg * 8 + i) * 64 + k];
                        acc[i][0] += xv.x * wa.x + xv.y * wa.y + xv.z * wa.z + xv.w * wa.w;
                        acc[i][1] += xv.x * wb.x + xv.y * wb.y + xv.z * wb.z + xv.w * wb.w;
                    }
                }
                float ba = b2[2 * jp], bb = b2[2 * jp + 1];
                #pragma unroll
                for (int i = 0; i < 8; i++) {
                    int row = rg * 8 + i;
                    h2t[(2 * jp) * 66 + row]     = fast_elu(acc[i][0] + ba);
                    h2t[(2 * jp + 1) * 66 + row] = fast_elu(acc[i][1] + bb);
                }
            }
            __syncthreads();

            // Stage 3: packed fp32x2 over row pairs
            for (int c0 = 0; c0 < OUTD; c0 += 128) {
                for (int f = tid; f < 64 * 128; f += 512) {
                    int c = f & 127; int k = f >> 7;
                    int cg = c0 + c;
                    w3s[k * 128 + c] = (cg < OUTD) ? w3[(size_t)k * OUTD + cg] : 0.f;
                }
                __syncthreads();

                if (act) {
                    u64 acc[4][4];
                    #pragma unroll
                    for (int rp = 0; rp < 4; rp++)
                        #pragma unroll
                        for (int qq = 0; qq < 4; qq++) acc[rp][qq] = 0ull;

                    #pragma unroll 4
                    for (int k = 0; k < H2; k++) {
                        u64 wd[4];
                        #pragma unroll
                        for (int qq = 0; qq < 4; qq++) {
                            float w = w3s[k * 128 + jp + 32 * qq];
                            wd[qq] = pack2(w, w);
                        }
                        const float* hp = &h2t[k * 66 + rg * 8];
                        u64 hv0 = *(const u64*)(hp + 0);
                        u64 hv1 = *(const u64*)(hp + 2);
                        u64 hv2 = *(const u64*)(hp + 4);
                        u64 hv3 = *(const u64*)(hp + 6);
                        #pragma unroll
                        for (int qq = 0; qq < 4; qq++) {
                            acc[0][qq] = ffma2(hv0, wd[qq], acc[0][qq]);
                            acc[1][qq] = ffma2(hv1, wd[qq], acc[1][qq]);
                            acc[2][qq] = ffma2(hv2, wd[qq], acc[2][qq]);
                            acc[3][qq] = ffma2(hv3, wd[qq], acc[3][qq]);
                        }
                    }

                    #pragma unroll
                    for (int qq = 0; qq < 4; qq++) {
                        int cg = c0 + jp + 32 * qq;
                        if (cg < OUTD) {
                            float bq = b3[cg];
                            #pragma unroll
                            for (int rp = 0; rp < 4; rp++) {
                                float2 v = unpack2(acc[rp][qq]);
                                size_t row = row0 + rg * 8 + 2 * rp;
                                out[row * OUTD + cg]       = v.x + bq;
                                out[(row + 1) * OUTD + cg] = v.y + bq;
                            }
                        }
                    }
                }
                __syncthreads();
            }
        }
    }
}

// ---------------------------------------------------------------------------
extern "C" void kernel_launch(void* const* d_in, const int* in_sizes, int n_in,
                              void* d_out, int out_size)
{
    const float* x    = (const float*)d_in[0];
    const float* h0   = (const float*)d_in[1];
    const float* w_ih = (const float*)d_in[2];
    const float* w_hh = (const float*)d_in[3];
    const float* b_ih = (const float*)d_in[4];
    const float* b_hh = (const float*)d_in[5];
    const float* w1   = (const float*)d_in[6];
    const float* b1   = (const float*)d_in[7];
    const float* w2   = (const float*)d_in[8];
    const float* b2   = (const float*)d_in[9];
    const float* w3   = (const float*)d_in[10];
    const float* b3   = (const float*)d_in[11];
    float* out = (float*)d_out;

    cudaFuncSetAttribute(fused_persist,
                         cudaFuncAttributeMaxDynamicSharedMemorySize, FUSED_SMEM);

    prep_w_kernel<<<(8 * 768 * 16 + 255) / 256, 256>>>(w_hh);

    fused_persist<<<GRID_P, 512, FUSED_SMEM>>>(h0, x, w_ih, b_ih, b_hh,
                                               w1, b1, w2, b2, w3, b3, out);
}

// round 14
// speedup vs baseline: 1.3863x; 1.3863x over previous
#include <cuda_runtime.h>
#include <cuda_bf16.h>
#include <math.h>
#include <string.h>

typedef unsigned int u32;
typedef unsigned long long u64;

// ---------------------------------------------------------------------------
// Problem constants
// ---------------------------------------------------------------------------
constexpr int T    = 64;
constexpr int B    = 2048;
constexpr int H    = 256;
constexpr int H1   = 64;
constexpr int H2   = 64;
constexpr int OUTD = 601;
constexpr int RROWS = 64;
constexpr int NTILE = T * B / RROWS;      // 2048 MLP tiles
constexpr int NCOPY = 8;                  // h_last copy tiles
constexpr int NTILE_TOT = NTILE + NCOPY;  // 2056

// ---------------------------------------------------------------------------
// PTX helpers
// ---------------------------------------------------------------------------
__device__ __forceinline__ u32 smem_u32(const void* p) {
    u32 a;
    asm("{ .reg .u64 t; cvta.to.shared.u64 t, %1; cvt.u32.u64 %0, t; }"
        : "=r"(a) : "l"(p));
    return a;
}
__device__ __forceinline__ void ldsm_x4(u32& r0, u32& r1, u32& r2, u32& r3, u32 addr) {
    asm volatile("ldmatrix.sync.aligned.m8n8.x4.shared.b16 {%0,%1,%2,%3}, [%4];"
                 : "=r"(r0), "=r"(r1), "=r"(r2), "=r"(r3) : "r"(addr));
}
__device__ __forceinline__ void mma_bf16(float* d, const u32* a, const u32* b) {
    asm volatile(
        "mma.sync.aligned.m16n8k16.row.col.f32.bf16.bf16.f32 "
        "{%0,%1,%2,%3}, {%4,%5,%6,%7}, {%8,%9}, {%0,%1,%2,%3};"
        : "+f"(d[0]), "+f"(d[1]), "+f"(d[2]), "+f"(d[3])
        : "r"(a[0]), "r"(a[1]), "r"(a[2]), "r"(a[3]), "r"(b[0]), "r"(b[1]));
}
__device__ __forceinline__ void cp16(u32 dst, const void* src) {
    asm volatile("cp.async.ca.shared.global [%0], [%1], 16;" :: "r"(dst), "l"(src));
}
__device__ __forceinline__ void cp_commit() {
    asm volatile("cp.async.commit_group;" ::: "memory");
}
template <int N>
__device__ __forceinline__ void cp_wait_group() {
    asm volatile("cp.async.wait_group %0;" :: "n"(N) : "memory");
}
__device__ __forceinline__ u32 bf2u(__nv_bfloat162 v) {
    u32 r; memcpy(&r, &v, 4); return r;
}
__device__ __forceinline__ float2 u2f2(u32 v) {
    __nv_bfloat162 b; memcpy(&b, &v, 4);
    return make_float2(__bfloat162float(b.x), __bfloat162float(b.y));
}
__device__ __forceinline__ u64 ffma2(u64 a, u64 b, u64 c) {
    u64 d; asm("fma.rn.f32x2 %0, %1, %2, %3;" : "=l"(d) : "l"(a), "l"(b), "l"(c));
    return d;
}
__device__ __forceinline__ u64 pack2(float x, float y) {
    u64 d; asm("mov.b64 %0, {%1, %2};" : "=l"(d) : "f"(x), "f"(y));
    return d;
}
__device__ __forceinline__ float2 unpack2(u64 v) {
    float2 r; asm("mov.b64 {%0, %1}, %2;" : "=f"(r.x), "=f"(r.y) : "l"(v));
    return r;
}
// named barriers (producer/consumer warp specialization)
#define BARS(id, n) asm volatile("bar.sync %0, %1;"   :: "n"(id), "n"(n) : "memory")
#define BARA(id, n) asm volatile("bar.arrive %0, %1;" :: "n"(id), "n"(n) : "memory")

constexpr float LOG2E = 1.4426950408889634f;
__device__ __forceinline__ float fast_sigmoid(float v) {
    float e; asm("ex2.approx.f32 %0, %1;" : "=f"(e) : "f"(-LOG2E * v));
    float r; asm("rcp.approx.f32 %0, %1;" : "=f"(r) : "f"(1.f + e));
    return r;
}
__device__ __forceinline__ float fast_tanh(float v) {
    float e; asm("ex2.approx.f32 %0, %1;" : "=f"(e) : "f"(2.f * LOG2E * v));
    float r; asm("rcp.approx.f32 %0, %1;" : "=f"(r) : "f"(1.f + e));
    return 1.f - 2.f * r;
}
__device__ __forceinline__ float fast_elu(float v) {
    if (v > 0.f) return v;
    float e; asm("ex2.approx.f32 %0, %1;" : "=f"(e) : "f"(LOG2E * v));
    return e - 1.f;
}

// ---------------------------------------------------------------------------
// Device scratch: h stored ONLY as t-indexed bf16 hi/lo
// ---------------------------------------------------------------------------
__device__ u32 g_hhi[(size_t)T * B * (H / 2)];
__device__ u32 g_hlo[(size_t)T * B * (H / 2)];
__device__ u32 g_cnt[32 * 32] = {};  // per-bg monotonic counters (128B apart)
__device__ u32 g_q = 0;              // work queue

// ---------------------------------------------------------------------------
// Single fused persistent kernel: 148 blocks x 512 threads (R12 skeleton,
// with named-barrier warp-specialized GRU pipeline instead of __syncthreads).
// ---------------------------------------------------------------------------
constexpr int GRID_P = 148;
constexpr int NGRU   = 128;
constexpr int SM_W      = 0;        // whi [4][192][128B]=98304 ; wlo at +98304
constexpr int SM_WLO_O  = 98304;
constexpr int SM_A      = 196608;   // 2 bufs x (hi 8192 + lo 8192)
constexpr int SM_PRM    = 229376;   // 7*64 f32
constexpr int SM_Q      = 231168;   // queue slot
constexpr int FUSED_SMEM = 231296;

struct AccT { float a[2][3][2][4]; };   // [mt][gate][sub][q]

__device__ __forceinline__ void mma_section32(AccT& A, u32 ab, u32 wb,
                                              int wm, int wn,
                                              int a_row, int a_colh,
                                              int b_row, int b_colh)
{
    #pragma unroll
    for (int ks = 0; ks < 4; ks++) {
        u32 ahi[2][4], alo[2][4];
        #pragma unroll
        for (int mt = 0; mt < 2; mt++) {
            int r = wm * 32 + mt * 16 + a_row;
            u32 off = (u32)(r * 128) + (u32)((ks * 32 + a_colh) ^ ((r & 7) << 4));
            ldsm_x4(ahi[mt][0], ahi[mt][1], ahi[mt][2], ahi[mt][3], ab + off);
            ldsm_x4(alo[mt][0], alo[mt][1], alo[mt][2], alo[mt][3], ab + 8192 + off);
        }
        #pragma unroll
        for (int g = 0; g < 3; g++) {
            int rr = g * 64 + wn * 16 + b_row;
            u32 off = (u32)(rr * 128) + (u32)((ks * 32 + b_colh) ^ ((rr & 7) << 4));
            u32 bh[4], bl[4];
            ldsm_x4(bh[0], bh[1], bh[2], bh[3], wb + off);
            ldsm_x4(bl[0], bl[1], bl[2], bl[3], wb + SM_WLO_O + off);
            #pragma unroll
            for (int mt = 0; mt < 2; mt++) {
                mma_bf16(A.a[mt][g][0], ahi[mt], bh);
                mma_bf16(A.a[mt][g][1], ahi[mt], bh + 2);
                mma_bf16(A.a[mt][g][0], ahi[mt], bl);
                mma_bf16(A.a[mt][g][1], ahi[mt], bl + 2);
                mma_bf16(A.a[mt][g][0], alo[mt], bh);
                mma_bf16(A.a[mt][g][1], alo[mt], bh + 2);
            }
        }
    }
}

__global__ void __launch_bounds__(512, 1)
fused_persist(const float* __restrict__ h0,
              const float* __restrict__ x,
              const float* __restrict__ w_ih,
              const float* __restrict__ w_hh,
              const float* __restrict__ b_ih,
              const float* __restrict__ b_hh,
              const float* __restrict__ w1, const float* __restrict__ b1,
              const float* __restrict__ w2, const float* __restrict__ b2,
              const float* __restrict__ w3, const float* __restrict__ b3,
              float* __restrict__ out)
{
    extern __shared__ char smem[];
    const u32 sb = smem_u32(smem);
    const int tid  = threadIdx.x;

    // =====================================================================
    // GRU producer part
    // =====================================================================
    if (blockIdx.x < NGRU) {
        float* sparam = (float*)(smem + SM_PRM);
        const int wid  = tid >> 5;
        const int lane = tid & 31;
        const int jc = blockIdx.x & 3;
        const int bg = blockIdx.x >> 2;
        const int j0 = jc * 64;
        const int b0 = bg * 64;
        const bool mmaw = wid < 8;
        const int wm = (wid >> 2) & 1;
        const int wn = wid & 3;
        const int stid = tid - 256;

        if (tid < 64) {
            int jg = j0 + tid;
            sparam[tid]        = w_ih[jg];
            sparam[64 + tid]   = w_ih[H + jg];
            sparam[128 + tid]  = w_ih[2 * H + jg];
            sparam[192 + tid]  = b_ih[jg]         + b_hh[jg];
            sparam[256 + tid]  = b_ih[H + jg]     + b_hh[H + jg];
            sparam[320 + tid]  = b_ih[2 * H + jg];
            sparam[384 + tid]  = b_hh[2 * H + jg];
        }

        // inline weight split: fp32 w_hh slice -> bf16 hi/lo, SW128, resident
        for (int c = 0; c < 4; c++) {
            for (int f = tid; f < 192 * 16; f += 512) {
                int rr = f >> 4, cc = f & 15;
                int g = rr >> 6, jj = rr & 63;
                float4 w = *(const float4*)&w_hh[((size_t)(g * H + j0 + jj)) * H
                                                 + c * 64 + cc * 4];
                __nv_bfloat162 h0p = __floats2bfloat162_rn(w.x, w.y);
                __nv_bfloat162 h1p = __floats2bfloat162_rn(w.z, w.w);
                __nv_bfloat162 l0p = __floats2bfloat162_rn(w.x - __bfloat162float(h0p.x),
                                                           w.y - __bfloat162float(h0p.y));
                __nv_bfloat162 l1p = __floats2bfloat162_rn(w.z - __bfloat162float(h1p.x),
                                                           w.w - __bfloat162float(h1p.y));
                u32 o = (u32)(c * 24576 + rr * 128) + (u32)((cc * 8) ^ ((rr & 7) << 4));
                *(u32*)(smem + SM_W + o)               = bf2u(h0p);
                *(u32*)(smem + SM_W + o + 4)           = bf2u(h1p);
                *(u32*)(smem + SM_W + SM_WLO_O + o)     = bf2u(l0p);
                *(u32*)(smem + SM_W + SM_WLO_O + o + 4) = bf2u(l1p);
            }
        }

        const int a_row  = lane & 15;
        const int a_colh = (lane >> 4) * 16;
        const int b_row  = ((lane >> 4) << 3) + (lane & 7);
        const int b_colh = ((lane >> 3) & 1) * 16;
        const int l4 = lane >> 2;
        const int lp = lane & 3;

        float2 hst[4][2];
        if (mmaw) {
            #pragma unroll
            for (int e = 0; e < 4; e++)
                #pragma unroll
                for (int sub = 0; sub < 2; sub++) {
                    int rowg = b0 + wm * 32 + (e >> 1) * 16 + (e & 1) * 8 + l4;
                    int jl = wn * 16 + 8 * sub + 2 * lp;
                    hst[e][sub] = *(const float2*)&h0[(size_t)rowg * H + j0 + jl];
                }
        }

        // pre-stage OWN chunk (jc) of h0 into buf0
        #pragma unroll
        for (int i = 0; i < 4; i++) {
            int f = tid + i * 512;
            int row = f >> 5, kp = f & 31;
            float2 hv = *(const float2*)&h0[(size_t)(b0 + row) * H + jc * 64 + 2 * kp];
            __nv_bfloat162 h2 = __floats2bfloat162_rn(hv.x, hv.y);
            __nv_bfloat162 l2 = __floats2bfloat162_rn(hv.x - __bfloat162float(h2.x),
                                                      hv.y - __bfloat162float(h2.y));
            u32 off = (u32)(row * 128) + (u32)((kp * 4) ^ ((row & 7) << 4));
            *(u32*)(smem + SM_A + off)        = bf2u(h2);
            *(u32*)(smem + SM_A + 8192 + off) = bf2u(l2);
        }
        __syncthreads();

        const u32 ab0 = sb + SM_A;
        const u32 ab1 = sb + SM_A + 16384;
        const int c1 = (jc + 1) & 3, c2 = (jc + 2) & 3, c3 = (jc + 3) & 3;

        #define STAGE_CP(c, dst)                                                 \
            do {                                                                 \
                size_t base_ = ((size_t)(t - 1) * B + b0) * 128 + (size_t)(c) * 32; \
                _Pragma("unroll")                                                \
                for (int i_ = 0; i_ < 2; i_++) {                                 \
                    int f_ = stid + i_ * 256;                                    \
                    int rr_ = f_ >> 3, cc_ = f_ & 7;                             \
                    u32 o_ = (u32)(rr_ * 128) + (u32)((cc_ * 16) ^ ((rr_ & 7) << 4)); \
                    cp16((dst) + o_,        &g_hhi[base_ + (size_t)rr_ * 128 + cc_ * 4]); \
                    cp16((dst) + 8192 + o_, &g_hlo[base_ + (size_t)rr_ * 128 + cc_ * 4]); \
                }                                                                \
                cp_commit();                                                     \
                cp_wait_group<0>();                                              \
            } while (0)

        #define STAGE_CVT(c, dstc)                                               \
            do {                                                                 \
                _Pragma("unroll")                                                \
                for (int i_ = 0; i_ < 8; i_++) {                                 \
                    int f_ = stid + i_ * 256;                                    \
                    int row_ = f_ >> 5, kp_ = f_ & 31;                           \
                    float2 hv_ = *(const float2*)&h0[(size_t)(b0 + row_) * H + (c) * 64 + 2 * kp_]; \
                    __nv_bfloat162 h2_ = __floats2bfloat162_rn(hv_.x, hv_.y);    \
                    __nv_bfloat162 l2_ = __floats2bfloat162_rn(                  \
                        hv_.x - __bfloat162float(h2_.x),                         \
                        hv_.y - __bfloat162float(h2_.y));                        \
                    u32 o_ = (u32)(row_ * 128) + (u32)((kp_ * 4) ^ ((row_ & 7) << 4)); \
                    *(u32*)((dstc) + o_)        = bf2u(h2_);                     \
                    *(u32*)((dstc) + 8192 + o_) = bf2u(l2_);                     \
                }                                                                \
            } while (0)

        // Named-barrier pipeline. Per step:
        //   staging: [sync6 if t>0] poll; stage c1->b1, arrive1; sync2;
        //            stage c2->b0, arrive3; sync4; stage c3->b1, arrive5.
        //   MMA:     own(b0), arrive2; sync1; c1(b1), arrive4; sync3;
        //            c2(b0); sync5; c3(b1), [arrive6 if t<T-1];
        //            sync7(256); epilogue(writes b0); fence; sync8(256);
        //            tid0 releases counter.
        for (int t = 0; t < T; t++) {
            if (mmaw) {
                AccT A;
                float xvv[4];
                #pragma unroll
                for (int mt = 0; mt < 2; mt++)
                    #pragma unroll
                    for (int g = 0; g < 3; g++)
                        #pragma unroll
                        for (int s = 0; s < 2; s++)
                            #pragma unroll
                            for (int q = 0; q < 4; q++) A.a[mt][g][s][q] = 0.f;
                #pragma unroll
                for (int e = 0; e < 4; e++)
                    xvv[e] = x[(size_t)t * B + b0 + wm * 32 + (e >> 1) * 16
                               + (e & 1) * 8 + l4];

                mma_section32(A, ab0, sb + SM_W + jc * 24576,
                              wm, wn, a_row, a_colh, b_row, b_colh);
                BARA(2, 512);
                BARS(1, 512);
                mma_section32(A, ab1, sb + SM_W + c1 * 24576,
                              wm, wn, a_row, a_colh, b_row, b_colh);
                BARA(4, 512);
                BARS(3, 512);
                mma_section32(A, ab0, sb + SM_W + c2 * 24576,
                              wm, wn, a_row, a_colh, b_row, b_colh);
                BARS(5, 512);
                mma_section32(A, ab1, sb + SM_W + c3 * 24576,
                              wm, wn, a_row, a_colh, b_row, b_colh);
                if (t < T - 1) BARA(6, 512);
                BARS(7, 256);   // all MMA warps done reading b0 (c2)

                // epilogue
                #pragma unroll
                for (int mt = 0; mt < 2; mt++)
                    #pragma unroll
                    for (int half = 0; half < 2; half++) {
                        int e = mt * 2 + half;
                        int rowl = wm * 32 + mt * 16 + half * 8 + l4;
                        int rowg = b0 + rowl;
                        float xv = xvv[e];
                        #pragma unroll
                        for (int sub = 0; sub < 2; sub++) {
                            int jl = wn * 16 + 8 * sub + 2 * lp;
                            float hn0, hn1;
                            {
                                int j = jl;
                                float r = fast_sigmoid(xv * sparam[j] + sparam[192 + j]
                                                       + A.a[mt][0][sub][half * 2]);
                                float z = fast_sigmoid(xv * sparam[64 + j] + sparam[256 + j]
                                                       + A.a[mt][1][sub][half * 2]);
                                float n = fast_tanh(xv * sparam[128 + j] + sparam[320 + j]
                                                    + r * (A.a[mt][2][sub][half * 2]
                                                           + sparam[384 + j]));
                                hn0 = (1.f - z) * n + z * hst[e][sub].x;
                            }
                            {
                                int j = jl + 1;
                                float r = fast_sigmoid(xv * sparam[j] + sparam[192 + j]
                                                       + A.a[mt][0][sub][half * 2 + 1]);
                                float z = fast_sigmoid(xv * sparam[64 + j] + sparam[256 + j]
                                                       + A.a[mt][1][sub][half * 2 + 1]);
                                float n = fast_tanh(xv * sparam[128 + j] + sparam[320 + j]
                                                    + r * (A.a[mt][2][sub][half * 2 + 1]
                                                           + sparam[384 + j]));
                                hn1 = (1.f - z) * n + z * hst[e][sub].y;
                            }
                            hst[e][sub] = make_float2(hn0, hn1);

                            __nv_bfloat162 h2 = __floats2bfloat162_rn(hn0, hn1);
                            __nv_bfloat162 l2 = __floats2bfloat162_rn(
                                hn0 - __bfloat162float(h2.x),
                                hn1 - __bfloat162float(h2.y));
                            int kp = wn * 8 + 4 * sub + lp;
                            size_t gi = ((size_t)t * B + rowg) * 128 + jc * 32 + kp;
                            u32 uhi = bf2u(h2), ulo = bf2u(l2);
                            g_hhi[gi] = uhi;
                            g_hlo[gi] = ulo;
                            u32 off = (u32)(rowl * 128)
                                      + (u32)((kp * 4) ^ ((rowl & 7) << 4));
                            *(u32*)(smem + SM_A + off)        = uhi;
                            *(u32*)(smem + SM_A + 8192 + off) = ulo;
                        }
                    }

                __threadfence();
                BARS(8, 256);
                if (tid == 0) atomicAdd(&g_cnt[bg * 32], 1u);
            } else {
                // ---- staging warps ----
                if (t > 0) {
                    BARS(6, 512);   // b1 free (c3 of t-1 consumed)
                    if (lane == 0) {
                        u32 g;
                        do {
                            asm volatile("ld.acquire.gpu.global.u32 %0, [%1];"
                                         : "=r"(g) : "l"(&g_cnt[bg * 32]));
                        } while ((int)(g - (u32)(4 * t)) < 0);
                    }
                    __syncwarp();
                    STAGE_CP(c1, ab1);
                } else {
                    STAGE_CVT(c1, smem + SM_A + 16384);
                }
                BARA(1, 512);
                BARS(2, 512);       // b0 free (own chunk consumed)
                if (t > 0) STAGE_CP(c2, ab0);
                else       STAGE_CVT(c2, smem + SM_A);
                BARA(3, 512);
                BARS(4, 512);       // b1 free (c1 consumed)
                if (t > 0) STAGE_CP(c3, ab1);
                else       STAGE_CVT(c3, smem + SM_A + 16384);
                BARA(5, 512);
            }
        }
        #undef STAGE_CP
        #undef STAGE_CVT
        __syncthreads();
    }

    // =====================================================================
    // Consumer part (all blocks): MLP tiles + h_last copy tiles
    // =====================================================================
    {
        float* sm  = (float*)smem;
        float* xt  = sm;            // [64][256]
        float* w1s = sm + 16384;    // [64][260]
        float* h1s = sm + 33024;    // [64][64]
        float* h2t = sm + 37120;    // [64][66]
        float* w3s = sm;            // alias xt
        float* w2s = sm + 16384;    // alias w1s
        u32* qs = (u32*)(smem + SM_Q);

        const int jp = tid & 31;
        const int rg = (tid >> 5) & 7;
        const bool act = tid < 256;

        for (;;) {
            __syncthreads();
            if (tid == 0) *qs = atomicAdd(&g_q, 1u);
            __syncthreads();
            u32 q = *qs;
            if (q >= (u32)NTILE_TOT) {
                if (q == (u32)(NTILE_TOT + GRID_P - 1) && tid == 0) {
                    for (int i = 0; i < 32; i++) g_cnt[i * 32] = 0;
                    __threadfence();
                    atomicExch(&g_q, 0u);
                }
                break;
            }

            if (q >= (u32)NTILE) {
                int seg = (int)(q - NTILE);
                if (tid < 4) {
                    u32 g;
                    do {
                        asm volatile("ld.acquire.gpu.global.u32 %0, [%1];"
                                     : "=r"(g) : "l"(&g_cnt[(seg * 4 + tid) * 32]));
                    } while ((int)(g - (u32)(4 * T)) < 0);
                }
                __syncthreads();
                size_t base = ((size_t)(T - 1) * B + (size_t)seg * 256) * 128;
                float* dst = out + (size_t)T * B * OUTD + (size_t)seg * 256 * H;
                for (int i = tid; i < 256 * 128; i += 512) {
                    float2 a = u2f2(g_hhi[base + i]);
                    float2 b = u2f2(g_hlo[base + i]);
                    *(float2*)&dst[2 * i] = make_float2(a.x + b.x, a.y + b.y);
                }
                continue;
            }

            int tt  = (int)(q >> 5);
            int bgq = (int)(q & 31);

            if (tid == 0) {
                u32 target = (u32)(4 * (tt + 1)), g;
                do {
                    asm volatile("ld.acquire.gpu.global.u32 %0, [%1];"
                                 : "=r"(g) : "l"(&g_cnt[bgq * 32]));
                } while ((int)(g - target) < 0);
            }
            __syncthreads();

            const size_t row0 = (size_t)q * RROWS;

            {
                const u32* hh = g_hhi + row0 * 128;
                const u32* ll = g_hlo + row0 * 128;
                for (int i = tid; i < RROWS * 128; i += 512) {
                    float2 a = u2f2(hh[i]);
                    float2 b = u2f2(ll[i]);
                    int row = i >> 7, kp = i & 127;
                    *(float2*)&xt[row * 256 + 2 * kp] = make_float2(a.x + b.x, a.y + b.y);
                }
            }
            for (int f = tid; f < H * H1; f += 512) {
                int jj = f & 63; int k = f >> 6;
                w1s[jj * 260 + k] = w1[f];
            }
            __syncthreads();

            // Stage 1
            if (act) {
                float acc[8][2];
                #pragma unroll
                for (int i = 0; i < 8; i++) { acc[i][0] = 0.f; acc[i][1] = 0.f; }
                #pragma unroll 4
                for (int k = 0; k < H; k += 4) {
                    float4 wa = *(const float4*)&w1s[(2 * jp) * 260 + k];
                    float4 wb = *(const float4*)&w1s[(2 * jp + 1) * 260 + k];
                    #pragma unroll
                    for (int i = 0; i < 8; i++) {
                        float4 xv = *(const float4*)&xt[(rg * 8 + i) * H + k];
                        acc[i][0] += xv.x * wa.x + xv.y * wa.y + xv.z * wa.z + xv.w * wa.w;
                        acc[i][1] += xv.x * wb.x + xv.y * wb.y + xv.z * wb.z + xv.w * wb.w;
                    }
                }
                float ba = b1[2 * jp], bb = b1[2 * jp + 1];
                #pragma unroll
                for (int i = 0; i < 8; i++) {
                    h1s[(rg * 8 + i) * 64 + 2 * jp]     = fast_elu(acc[i][0] + ba);
                    h1s[(rg * 8 + i) * 64 + 2 * jp + 1] = fast_elu(acc[i][1] + bb);
                }
            }
            __syncthreads();

            for (int f = tid; f < H1 * H2; f += 512) {
                int jj = f & 63; int k = f >> 6;
                w2s[jj * 68 + k] = w2[f];
            }
            __syncthreads();

            // Stage 2 (h2 transposed)
            if (act) {
                float acc[8][2];
                #pragma unroll
                for (int i = 0; i < 8; i++) { acc[i][0] = 0.f; acc[i][1] = 0.f; }
                #pragma unroll
                for (int k = 0; k < H1; k += 4) {
                    float4 wa = *(const float4*)&w2s[(2 * jp) * 68 + k];
                    float4 wb = *(const float4*)&w2s[(2 * jp + 1) * 68 + k];
                    #pragma unroll
                    for (int i = 0; i < 8; i++) {
                        float4 xv = *(const float4*)&h1s[(rg * 8 + i) * 64 + k];
                        acc[i][0] += xv.x * wa.x + xv.y * wa.y + xv.z * wa.z + xv.w * wa.w;
                        acc[i][1] += xv.x * wb.x + xv.y * wb.y + xv.z * wb.z + xv.w * wb.w;
                    }
                }
                float ba = b2[2 * jp], bb = b2[2 * jp + 1];
                #pragma unroll
                for (int i = 0; i < 8; i++) {
                    int row = rg * 8 + i;
                    h2t[(2 * jp) * 66 + row]     = fast_elu(acc[i][0] + ba);
                    h2t[(2 * jp + 1) * 66 + row] = fast_elu(acc[i][1] + bb);
                }
            }
            __syncthreads();

            // Stage 3: packed fp32x2 over row pairs
            for (int c0 = 0; c0 < OUTD; c0 += 128) {
                for (int f = tid; f < 64 * 128; f += 512) {
                    int c = f & 127; int k = f >> 7;
                    int cg = c0 + c;
                    w3s[k * 128 + c] = (cg < OUTD) ? w3[(size_t)k * OUTD + cg] : 0.f;
                }
                __syncthreads();

                if (act) {
                    u64 acc[4][4];
                    #pragma unroll
                    for (int rp = 0; rp < 4; rp++)
                        #pragma unroll
                        for (int qq = 0; qq < 4; qq++) acc[rp][qq] = 0ull;

                    #pragma unroll 4
                    for (int k = 0; k < H2; k++) {
                        u64 wd[4];
                        #pragma unroll
                        for (int qq = 0; qq < 4; qq++) {
                            float w = w3s[k * 128 + jp + 32 * qq];
                            wd[qq] = pack2(w, w);
                        }
                        const float* hp = &h2t[k * 66 + rg * 8];
                        u64 hv0 = *(const u64*)(hp + 0);
                        u64 hv1 = *(const u64*)(hp + 2);
                        u64 hv2 = *(const u64*)(hp + 4);
                        u64 hv3 = *(const u64*)(hp + 6);
                        #pragma unroll
                        for (int qq = 0; qq < 4; qq++) {
                            acc[0][qq] = ffma2(hv0, wd[qq], acc[0][qq]);
                            acc[1][qq] = ffma2(hv1, wd[qq], acc[1][qq]);
                            acc[2][qq] = ffma2(hv2, wd[qq], acc[2][qq]);
                            acc[3][qq] = ffma2(hv3, wd[qq], acc[3][qq]);
                        }
                    }

                    #pragma unroll
                    for (int qq = 0; qq < 4; qq++) {
                        int cg = c0 + jp + 32 * qq;
                        if (cg < OUTD) {
                            float bq = b3[cg];
                            #pragma unroll
                            for (int rp = 0; rp < 4; rp++) {
                                float2 v = unpack2(acc[rp][qq]);
                                size_t row = row0 + rg * 8 + 2 * rp;
                                out[row * OUTD + cg]       = v.x + bq;
                                out[(row + 1) * OUTD + cg] = v.y + bq;
                            }
                        }
                    }
                }
                __syncthreads();
            }
        }
    }
}

// ---------------------------------------------------------------------------
extern "C" void kernel_launch(void* const* d_in, const int* in_sizes, int n_in,
                              void* d_out, int out_size)
{
    const float* x    = (const float*)d_in[0];
    const float* h0   = (const float*)d_in[1];
    const float* w_ih = (const float*)d_in[2];
    const float* w_hh = (const float*)d_in[3];
    const float* b_ih = (const float*)d_in[4];
    const float* b_hh = (const float*)d_in[5];
    const float* w1   = (const float*)d_in[6];
    const float* b1   = (const float*)d_in[7];
    const float* w2   = (const float*)d_in[8];
    const float* b2   = (const float*)d_in[9];
    const float* w3   = (const float*)d_in[10];
    const float* b3   = (const float*)d_in[11];
    float* out = (float*)d_out;

    cudaFuncSetAttribute(fused_persist,
                         cudaFuncAttributeMaxDynamicSharedMemorySize, FUSED_SMEM);

    fused_persist<<<GRID_P, 512, FUSED_SMEM>>>(h0, x, w_ih, w_hh, b_ih, b_hh,
                                               w1, b1, w2, b2, w3, b3, out);
}

// round 15
// speedup vs baseline: 1.6164x; 1.1660x over previous
#include <cuda_runtime.h>
#include <cuda_bf16.h>
#include <cuda_fp16.h>
#include <math.h>
#include <string.h>

typedef unsigned int u32;
typedef unsigned long long u64;

// ---------------------------------------------------------------------------
// Problem constants
// ---------------------------------------------------------------------------
constexpr int T    = 64;
constexpr int B    = 2048;
constexpr int H    = 256;
constexpr int H1   = 64;
constexpr int H2   = 64;
constexpr int OUTD = 601;
constexpr int RROWS = 64;
constexpr int NTILE = T * B / RROWS;      // 2048 MLP tiles
constexpr int NCOPY = 8;
constexpr int NTILE_TOT = NTILE + NCOPY;  // 2056

// ---------------------------------------------------------------------------
// PTX helpers
// ---------------------------------------------------------------------------
__device__ __forceinline__ u32 smem_u32(const void* p) {
    u32 a;
    asm("{ .reg .u64 t; cvta.to.shared.u64 t, %1; cvt.u32.u64 %0, t; }"
        : "=r"(a) : "l"(p));
    return a;
}
__device__ __forceinline__ void ldsm_x4(u32& r0, u32& r1, u32& r2, u32& r3, u32 addr) {
    asm volatile("ldmatrix.sync.aligned.m8n8.x4.shared.b16 {%0,%1,%2,%3}, [%4];"
                 : "=r"(r0), "=r"(r1), "=r"(r2), "=r"(r3) : "r"(addr));
}
__device__ __forceinline__ void mma_f16(float* d, const u32* a, const u32* b) {
    asm volatile(
        "mma.sync.aligned.m16n8k16.row.col.f32.f16.f16.f32 "
        "{%0,%1,%2,%3}, {%4,%5,%6,%7}, {%8,%9}, {%0,%1,%2,%3};"
        : "+f"(d[0]), "+f"(d[1]), "+f"(d[2]), "+f"(d[3])
        : "r"(a[0]), "r"(a[1]), "r"(a[2]), "r"(a[3]), "r"(b[0]), "r"(b[1]));
}
__device__ __forceinline__ u32 bf2u(__nv_bfloat162 v) {
    u32 r; memcpy(&r, &v, 4); return r;
}
__device__ __forceinline__ float2 u2f2(u32 v) {
    __nv_bfloat162 b; memcpy(&b, &v, 4);
    return make_float2(__bfloat162float(b.x), __bfloat162float(b.y));
}
__device__ __forceinline__ u32 f2h2(float x, float y) {
    __half2 h = __floats2half2_rn(x, y);
    u32 r; memcpy(&r, &h, 4); return r;
}
__device__ __forceinline__ u64 ffma2(u64 a, u64 b, u64 c) {
    u64 d; asm("fma.rn.f32x2 %0, %1, %2, %3;" : "=l"(d) : "l"(a), "l"(b), "l"(c));
    return d;
}
__device__ __forceinline__ u64 pack2(float x, float y) {
    u64 d; asm("mov.b64 %0, {%1, %2};" : "=l"(d) : "f"(x), "f"(y));
    return d;
}
__device__ __forceinline__ float2 unpack2(u64 v) {
    float2 r; asm("mov.b64 {%0, %1}, %2;" : "=f"(r.x), "=f"(r.y) : "l"(v));
    return r;
}
#define BARS(id, n) asm volatile("bar.sync %0, %1;"   :: "n"(id), "n"(n) : "memory")
#define BARA(id, n) asm volatile("bar.arrive %0, %1;" :: "n"(id), "n"(n) : "memory")

constexpr float LOG2E = 1.4426950408889634f;
__device__ __forceinline__ float fast_sigmoid(float v) {
    float e; asm("ex2.approx.f32 %0, %1;" : "=f"(e) : "f"(-LOG2E * v));
    float r; asm("rcp.approx.f32 %0, %1;" : "=f"(r) : "f"(1.f + e));
    return r;
}
__device__ __forceinline__ float fast_tanh(float v) {
    float e; asm("ex2.approx.f32 %0, %1;" : "=f"(e) : "f"(2.f * LOG2E * v));
    float r; asm("rcp.approx.f32 %0, %1;" : "=f"(r) : "f"(1.f + e));
    return 1.f - 2.f * r;
}
__device__ __forceinline__ float fast_elu(float v) {
    if (v > 0.f) return v;
    float e; asm("ex2.approx.f32 %0, %1;" : "=f"(e) : "f"(LOG2E * v));
    return e - 1.f;
}

// ---------------------------------------------------------------------------
// Device scratch: h stored as t-indexed bf16 hi/lo (16-bit accurate; MLP input)
// ---------------------------------------------------------------------------
__device__ u32 g_hhi[(size_t)T * B * (H / 2)];
__device__ u32 g_hlo[(size_t)T * B * (H / 2)];
__device__ u32 g_cnt[32 * 32] = {};
__device__ u32 g_q = 0;

// ---------------------------------------------------------------------------
// Single fused persistent kernel: 148 blocks x 512 threads.
// GRU (blocks 0..127): single-term fp16 HMMA (W fp16 resident 96KB; A = 4
// resident fp16 chunk-buffers). 8 MMA warps + 8 staging warps; one bar-wait
// per step. Consumers: MLP tiles + h_last copy tiles from a queue.
// ---------------------------------------------------------------------------
constexpr int GRID_P = 148;
constexpr int NGRU   = 128;
constexpr int SM_W   = 0;          // [4 chunks][192 rows][128B] = 98304
constexpr int SM_A   = 98304;      // 4 bufs x 8192 (64 rows x 128B fp16)
constexpr int SM_PRM = 131072;     // 7*64 f32
constexpr int SM_Q   = 165376;     // queue slot (above MLP region)
constexpr int FUSED_SMEM = 165504;

__device__ __forceinline__ void mma_sec(float A[2][3][2][4], u32 ab, u32 wb,
                                        int wm, int wn,
                                        int a_row, int a_colh,
                                        int b_row, int b_colh)
{
    #pragma unroll
    for (int ks = 0; ks < 4; ks++) {
        u32 av[2][4];
        #pragma unroll
        for (int mt = 0; mt < 2; mt++) {
            int r = wm * 32 + mt * 16 + a_row;
            u32 off = (u32)(r * 128) + (u32)((ks * 32 + a_colh) ^ ((r & 7) << 4));
            ldsm_x4(av[mt][0], av[mt][1], av[mt][2], av[mt][3], ab + off);
        }
        #pragma unroll
        for (int g = 0; g < 3; g++) {
            int rr = g * 64 + wn * 16 + b_row;
            u32 off = (u32)(rr * 128) + (u32)((ks * 32 + b_colh) ^ ((rr & 7) << 4));
            u32 bh[4];
            ldsm_x4(bh[0], bh[1], bh[2], bh[3], wb + off);
            #pragma unroll
            for (int mt = 0; mt < 2; mt++) {
                mma_f16(A[mt][g][0], av[mt], bh);
                mma_f16(A[mt][g][1], av[mt], bh + 2);
            }
        }
    }
}

__global__ void __launch_bounds__(512, 1)
fused_persist(const float* __restrict__ h0,
              const float* __restrict__ x,
              const float* __restrict__ w_ih,
              const float* __restrict__ w_hh,
              const float* __restrict__ b_ih,
              const float* __restrict__ b_hh,
              const float* __restrict__ w1, const float* __restrict__ b1,
              const float* __restrict__ w2, const float* __restrict__ b2,
              const float* __restrict__ w3, const float* __restrict__ b3,
              float* __restrict__ out)
{
    extern __shared__ char smem[];
    const u32 sb = smem_u32(smem);
    const int tid  = threadIdx.x;

    // =====================================================================
    // GRU producer part
    // =====================================================================
    if (blockIdx.x < NGRU) {
        float* sparam = (float*)(smem + SM_PRM);
        const int wid  = tid >> 5;
        const int lane = tid & 31;
        const int jc = blockIdx.x & 3;
        const int bg = blockIdx.x >> 2;
        const int j0 = jc * 64;
        const int b0 = bg * 64;
        const bool mmaw = wid < 8;
        const int wm = (wid >> 2) & 1;
        const int wn = wid & 3;
        const int stid = tid - 256;

        if (tid < 64) {
            int jg = j0 + tid;
            sparam[tid]        = w_ih[jg];
            sparam[64 + tid]   = w_ih[H + jg];
            sparam[128 + tid]  = w_ih[2 * H + jg];
            sparam[192 + tid]  = b_ih[jg]         + b_hh[jg];
            sparam[256 + tid]  = b_ih[H + jg]     + b_hh[H + jg];
            sparam[320 + tid]  = b_ih[2 * H + jg];
            sparam[384 + tid]  = b_hh[2 * H + jg];
        }

        // W: fp32 -> single fp16, SW128, resident: [c][rr=g*64+jj][128B]
        for (int c = 0; c < 4; c++) {
            for (int f = tid; f < 192 * 16; f += 512) {
                int rr = f >> 4, cc = f & 15;
                int g = rr >> 6, jj = rr & 63;
                float4 w = *(const float4*)&w_hh[((size_t)(g * H + j0 + jj)) * H
                                                 + c * 64 + cc * 4];
                u32 o = (u32)(c * 24576 + rr * 128) + (u32)((cc * 8) ^ ((rr & 7) << 4));
                *(u32*)(smem + SM_W + o)     = f2h2(w.x, w.y);
                *(u32*)(smem + SM_W + o + 4) = f2h2(w.z, w.w);
            }
        }

        const int a_row  = lane & 15;
        const int a_colh = (lane >> 4) * 16;
        const int b_row  = ((lane >> 4) << 3) + (lane & 7);
        const int b_colh = ((lane >> 3) & 1) * 16;
        const int l4 = lane >> 2;
        const int lp = lane & 3;

        float2 hst[4][2];
        if (mmaw) {
            #pragma unroll
            for (int e = 0; e < 4; e++)
                #pragma unroll
                for (int sub = 0; sub < 2; sub++) {
                    int rowg = b0 + wm * 32 + (e >> 1) * 16 + (e & 1) * 8 + l4;
                    int jl = wn * 16 + 8 * sub + 2 * lp;
                    hst[e][sub] = *(const float2*)&h0[(size_t)rowg * H + j0 + jl];
                }
        }

        // pre-stage OWN chunk (jc) of h0 into buf[jc] as fp16
        #pragma unroll
        for (int i = 0; i < 4; i++) {
            int f = tid + i * 512;
            int row = f >> 5, kp = f & 31;
            float2 hv = *(const float2*)&h0[(size_t)(b0 + row) * H + jc * 64 + 2 * kp];
            u32 off = (u32)(row * 128) + (u32)((kp * 4) ^ ((row & 7) << 4));
            *(u32*)(smem + SM_A + jc * 8192 + off) = f2h2(hv.x, hv.y);
        }
        __syncthreads();

        const int c1 = (jc + 1) & 3, c2 = (jc + 2) & 3, c3 = (jc + 3) & 3;
        const int srr = stid >> 2;     // staging row 0..63
        const int sq  = stid & 3;      // staging quarter (8 u32 of 32)

        for (int t = 0; t < T; t++) {
            if (mmaw) {
                float A[2][3][2][4];
                float xvv[4];
                #pragma unroll
                for (int mt = 0; mt < 2; mt++)
                    #pragma unroll
                    for (int g = 0; g < 3; g++)
                        #pragma unroll
                        for (int s = 0; s < 2; s++)
                            #pragma unroll
                            for (int q = 0; q < 4; q++) A[mt][g][s][q] = 0.f;
                #pragma unroll
                for (int e = 0; e < 4; e++)
                    xvv[e] = x[(size_t)t * B + b0 + wm * 32 + (e >> 1) * 16
                               + (e & 1) * 8 + l4];

                // own chunk (no wait), then one wait, then unbroken c1..c3
                mma_sec(A, sb + SM_A + jc * 8192, sb + SM_W + jc * 24576,
                        wm, wn, a_row, a_colh, b_row, b_colh);
                BARS(1, 512);
                mma_sec(A, sb + SM_A + c1 * 8192, sb + SM_W + c1 * 24576,
                        wm, wn, a_row, a_colh, b_row, b_colh);
                mma_sec(A, sb + SM_A + c2 * 8192, sb + SM_W + c2 * 24576,
                        wm, wn, a_row, a_colh, b_row, b_colh);
                mma_sec(A, sb + SM_A + c3 * 8192, sb + SM_W + c3 * 24576,
                        wm, wn, a_row, a_colh, b_row, b_colh);
                if (t < T - 1) BARA(2, 512);

                // epilogue
                #pragma unroll
                for (int mt = 0; mt < 2; mt++)
                    #pragma unroll
                    for (int half = 0; half < 2; half++) {
                        int e = mt * 2 + half;
                        int rowl = wm * 32 + mt * 16 + half * 8 + l4;
                        int rowg = b0 + rowl;
                        float xv = xvv[e];
                        #pragma unroll
                        for (int sub = 0; sub < 2; sub++) {
                            int jl = wn * 16 + 8 * sub + 2 * lp;
                            float hn0, hn1;
                            {
                                int j = jl;
                                float r = fast_sigmoid(xv * sparam[j] + sparam[192 + j]
                                                       + A[mt][0][sub][half * 2]);
                                float z = fast_sigmoid(xv * sparam[64 + j] + sparam[256 + j]
                                                       + A[mt][1][sub][half * 2]);
                                float n = fast_tanh(xv * sparam[128 + j] + sparam[320 + j]
                                                    + r * (A[mt][2][sub][half * 2]
                                                           + sparam[384 + j]));
                                hn0 = (1.f - z) * n + z * hst[e][sub].x;
                            }
                            {
                                int j = jl + 1;
                                float r = fast_sigmoid(xv * sparam[j] + sparam[192 + j]
                                                       + A[mt][0][sub][half * 2 + 1]);
                                float z = fast_sigmoid(xv * sparam[64 + j] + sparam[256 + j]
                                                       + A[mt][1][sub][half * 2 + 1]);
                                float n = fast_tanh(xv * sparam[128 + j] + sparam[320 + j]
                                                    + r * (A[mt][2][sub][half * 2 + 1]
                                                           + sparam[384 + j]));
                                hn1 = (1.f - z) * n + z * hst[e][sub].y;
                            }
                            hst[e][sub] = make_float2(hn0, hn1);

                            // 16-bit bf16 hi/lo to global (consumers + siblings)
                            __nv_bfloat162 h2 = __floats2bfloat162_rn(hn0, hn1);
                            __nv_bfloat162 l2 = __floats2bfloat162_rn(
                                hn0 - __bfloat162float(h2.x),
                                hn1 - __bfloat162float(h2.y));
                            int kp = wn * 8 + 4 * sub + lp;
                            size_t gi = ((size_t)t * B + rowg) * 128 + jc * 32 + kp;
                            g_hhi[gi] = bf2u(h2);
                            g_hlo[gi] = bf2u(l2);
                            // own chunk fp16 into buf[jc] for next step
                            u32 off = (u32)(rowl * 128)
                                      + (u32)((kp * 4) ^ ((rowl & 7) << 4));
                            *(u32*)(smem + SM_A + jc * 8192 + off) = f2h2(hn0, hn1);
                        }
                    }

                __threadfence();
                BARS(3, 256);
                if (tid == 0) atomicAdd(&g_cnt[bg * 32], 1u);
            } else {
                // ---- staging warps: one poll, stage all 3 sibling chunks ----
                if (t > 0) {
                    BARS(2, 512);   // MMA done reading bufs c1..c3 of step t-1
                    if (lane == 0) {
                        u32 g;
                        do {
                            asm volatile("ld.acquire.gpu.global.u32 %0, [%1];"
                                         : "=r"(g) : "l"(&g_cnt[bg * 32]));
                        } while ((int)(g - (u32)(4 * t)) < 0);
                    }
                    __syncwarp();
                    const int cs[3] = {c1, c2, c3};
                    #pragma unroll
                    for (int ci = 0; ci < 3; ci++) {
                        int c = cs[ci];
                        size_t base = ((size_t)(t - 1) * B + b0 + srr) * 128
                                      + (size_t)c * 32 + sq * 8;
                        uint4 ha = *(const uint4*)&g_hhi[base];
                        uint4 hb = *(const uint4*)&g_hhi[base + 4];
                        uint4 la = *(const uint4*)&g_hlo[base];
                        uint4 lb = *(const uint4*)&g_hlo[base + 4];
                        u32 o[8];
                        {
                            float2 p, q2;
                            p = u2f2(ha.x); q2 = u2f2(la.x); o[0] = f2h2(p.x + q2.x, p.y + q2.y);
                            p = u2f2(ha.y); q2 = u2f2(la.y); o[1] = f2h2(p.x + q2.x, p.y + q2.y);
                            p = u2f2(ha.z); q2 = u2f2(la.z); o[2] = f2h2(p.x + q2.x, p.y + q2.y);
                            p = u2f2(ha.w); q2 = u2f2(la.w); o[3] = f2h2(p.x + q2.x, p.y + q2.y);
                            p = u2f2(hb.x); q2 = u2f2(lb.x); o[4] = f2h2(p.x + q2.x, p.y + q2.y);
                            p = u2f2(hb.y); q2 = u2f2(lb.y); o[5] = f2h2(p.x + q2.x, p.y + q2.y);
                            p = u2f2(hb.z); q2 = u2f2(lb.z); o[6] = f2h2(p.x + q2.x, p.y + q2.y);
                            p = u2f2(hb.w); q2 = u2f2(lb.w); o[7] = f2h2(p.x + q2.x, p.y + q2.y);
                        }
                        u32 d0 = (u32)(srr * 128) + (u32)((sq * 32) ^ ((srr & 7) << 4));
                        u32 d1 = (u32)(srr * 128) + (u32)((sq * 32 + 16) ^ ((srr & 7) << 4));
                        char* bufc = smem + SM_A + c * 8192;
                        *(uint4*)(bufc + d0) = make_uint4(o[0], o[1], o[2], o[3]);
                        *(uint4*)(bufc + d1) = make_uint4(o[4], o[5], o[6], o[7]);
                    }
                } else {
                    const int cs[3] = {c1, c2, c3};
                    #pragma unroll
                    for (int ci = 0; ci < 3; ci++) {
                        int c = cs[ci];
                        const float* src = &h0[(size_t)(b0 + srr) * H + c * 64 + sq * 16];
                        u32 o[8];
                        #pragma unroll
                        for (int v = 0; v < 4; v++) {
                            float4 w = *(const float4*)(src + v * 4);
                            o[2 * v]     = f2h2(w.x, w.y);
                            o[2 * v + 1] = f2h2(w.z, w.w);
                        }
                        u32 d0 = (u32)(srr * 128) + (u32)((sq * 32) ^ ((srr & 7) << 4));
                        u32 d1 = (u32)(srr * 128) + (u32)((sq * 32 + 16) ^ ((srr & 7) << 4));
                        char* bufc = smem + SM_A + c * 8192;
                        *(uint4*)(bufc + d0) = make_uint4(o[0], o[1], o[2], o[3]);
                        *(uint4*)(bufc + d1) = make_uint4(o[4], o[5], o[6], o[7]);
                    }
                }
                BARA(1, 512);
            }
        }
        __syncthreads();
    }

    // =====================================================================
    // Consumer part (all blocks): MLP tiles + h_last copy tiles
    // =====================================================================
    {
        float* sm  = (float*)smem;
        float* xt  = sm;            // [64][256]
        float* w1s = sm + 16384;    // [64][260]
        float* h1s = sm + 33024;    // [64][64]
        float* h2t = sm + 37120;    // [64][66]
        float* w3s = sm;            // alias xt
        float* w2s = sm + 16384;    // alias w1s
        u32* qs = (u32*)(smem + SM_Q);

        const int jp = tid & 31;
        const int rg = (tid >> 5) & 7;
        const bool act = tid < 256;

        for (;;) {
            __syncthreads();
            if (tid == 0) *qs = atomicAdd(&g_q, 1u);
            __syncthreads();
            u32 q = *qs;
            if (q >= (u32)NTILE_TOT) {
                if (q == (u32)(NTILE_TOT + GRID_P - 1) && tid == 0) {
                    for (int i = 0; i < 32; i++) g_cnt[i * 32] = 0;
                    __threadfence();
                    atomicExch(&g_q, 0u);
                }
                break;
            }

            if (q >= (u32)NTILE) {
                int seg = (int)(q - NTILE);
                if (tid < 4) {
                    u32 g;
                    do {
                        asm volatile("ld.acquire.gpu.global.u32 %0, [%1];"
                                     : "=r"(g) : "l"(&g_cnt[(seg * 4 + tid) * 32]));
                    } while ((int)(g - (u32)(4 * T)) < 0);
                }
                __syncthreads();
                size_t base = ((size_t)(T - 1) * B + (size_t)seg * 256) * 128;
                float* dst = out + (size_t)T * B * OUTD + (size_t)seg * 256 * H;
                for (int i = tid; i < 256 * 128; i += 512) {
                    float2 a = u2f2(g_hhi[base + i]);
                    float2 b = u2f2(g_hlo[base + i]);
                    *(float2*)&dst[2 * i] = make_float2(a.x + b.x, a.y + b.y);
                }
                continue;
            }

            int tt  = (int)(q >> 5);
            int bgq = (int)(q & 31);

            if (tid == 0) {
                u32 target = (u32)(4 * (tt + 1)), g;
                do {
                    asm volatile("ld.acquire.gpu.global.u32 %0, [%1];"
                                 : "=r"(g) : "l"(&g_cnt[bgq * 32]));
                } while ((int)(g - target) < 0);
            }
            __syncthreads();

            const size_t row0 = (size_t)q * RROWS;

            {
                const u32* hh = g_hhi + row0 * 128;
                const u32* ll = g_hlo + row0 * 128;
                for (int i = tid; i < RROWS * 128; i += 512) {
                    float2 a = u2f2(hh[i]);
                    float2 b = u2f2(ll[i]);
                    int row = i >> 7, kp = i & 127;
                    *(float2*)&xt[row * 256 + 2 * kp] = make_float2(a.x + b.x, a.y + b.y);
                }
            }
            for (int f = tid; f < H * H1; f += 512) {
                int jj = f & 63; int k = f >> 6;
                w1s[jj * 260 + k] = w1[f];
            }
            __syncthreads();

            // Stage 1
            if (act) {
                float acc[8][2];
                #pragma unroll
                for (int i = 0; i < 8; i++) { acc[i][0] = 0.f; acc[i][1] = 0.f; }
                #pragma unroll 4
                for (int k = 0; k < H; k += 4) {
                    float4 wa = *(const float4*)&w1s[(2 * jp) * 260 + k];
                    float4 wb = *(const float4*)&w1s[(2 * jp + 1) * 260 + k];
                    #pragma unroll
                    for (int i = 0; i < 8; i++) {
                        float4 xv = *(const float4*)&xt[(rg * 8 + i) * H + k];
                        acc[i][0] += xv.x * wa.x + xv.y * wa.y + xv.z * wa.z + xv.w * wa.w;
                        acc[i][1] += xv.x * wb.x + xv.y * wb.y + xv.z * wb.z + xv.w * wb.w;
                    }
                }
                float ba = b1[2 * jp], bb = b1[2 * jp + 1];
                #pragma unroll
                for (int i = 0; i < 8; i++) {
                    h1s[(rg * 8 + i) * 64 + 2 * jp]     = fast_elu(acc[i][0] + ba);
                    h1s[(rg * 8 + i) * 64 + 2 * jp + 1] = fast_elu(acc[i][1] + bb);
                }
            }
            __syncthreads();

            for (int f = tid; f < H1 * H2; f += 512) {
                int jj = f & 63; int k = f >> 6;
                w2s[jj * 68 + k] = w2[f];
            }
            __syncthreads();

            // Stage 2 (h2 transposed)
            if (act) {
                float acc[8][2];
                #pragma unroll
                for (int i = 0; i < 8; i++) { acc[i][0] = 0.f; acc[i][1] = 0.f; }
                #pragma unroll
                for (int k = 0; k < H1; k += 4) {
                    float4 wa = *(const float4*)&w2s[(2 * jp) * 68 + k];
                    float4 wb = *(const float4*)&w2s[(2 * jp + 1) * 68 + k];
                    #pragma unroll
                    for (int i = 0; i < 8; i++) {
                        float4 xv = *(const float4*)&h1s[(rg * 8 + i) * 64 + k];
                        acc[i][0] += xv.x * wa.x + xv.y * wa.y + xv.z * wa.z + xv.w * wa.w;
                        acc[i][1] += xv.x * wb.x + xv.y * wb.y + xv.z * wb.z + xv.w * wb.w;
                    }
                }
                float ba = b2[2 * jp], bb = b2[2 * jp + 1];
                #pragma unroll
                for (int i = 0; i < 8; i++) {
                    int row = rg * 8 + i;
                    h2t[(2 * jp) * 66 + row]     = fast_elu(acc[i][0] + ba);
                    h2t[(2 * jp + 1) * 66 + row] = fast_elu(acc[i][1] + bb);
                }
            }
            __syncthreads();

            // Stage 3: packed fp32x2 over row pairs
            for (int c0 = 0; c0 < OUTD; c0 += 128) {
                for (int f = tid; f < 64 * 128; f += 512) {
                    int c = f & 127; int k = f >> 7;
                    int cg = c0 + c;
                    w3s[k * 128 + c] = (cg < OUTD) ? w3[(size_t)k * OUTD + cg] : 0.f;
                }
                __syncthreads();

                if (act) {
                    u64 acc[4][4];
                    #pragma unroll
                    for (int rp = 0; rp < 4; rp++)
                        #pragma unroll
                        for (int qq = 0; qq < 4; qq++) acc[rp][qq] = 0ull;

                    #pragma unroll 4
                    for (int k = 0; k < H2; k++) {
                        u64 wd[4];
                        #pragma unroll
                        for (int qq = 0; qq < 4; qq++) {
                            float w = w3s[k * 128 + jp + 32 * qq];
                            wd[qq] = pack2(w, w);
                        }
                        const float* hp = &h2t[k * 66 + rg * 8];
                        u64 hv0 = *(const u64*)(hp + 0);
                        u64 hv1 = *(const u64*)(hp + 2);
                        u64 hv2 = *(const u64*)(hp + 4);
                        u64 hv3 = *(const u64*)(hp + 6);
                        #pragma unroll
                        for (int qq = 0; qq < 4; qq++) {
                            acc[0][qq] = ffma2(hv0, wd[qq], acc[0][qq]);
                            acc[1][qq] = ffma2(hv1, wd[qq], acc[1][qq]);
                            acc[2][qq] = ffma2(hv2, wd[qq], acc[2][qq]);
                            acc[3][qq] = ffma2(hv3, wd[qq], acc[3][qq]);
                        }
                    }

                    #pragma unroll
                    for (int qq = 0; qq < 4; qq++) {
                        int cg = c0 + jp + 32 * qq;
                        if (cg < OUTD) {
                            float bq = b3[cg];
                            #pragma unroll
                            for (int rp = 0; rp < 4; rp++) {
                                float2 v = unpack2(acc[rp][qq]);
                                size_t row = row0 + rg * 8 + 2 * rp;
                                out[row * OUTD + cg]       = v.x + bq;
                                out[(row + 1) * OUTD + cg] = v.y + bq;
                            }
                        }
                    }
                }
                __syncthreads();
            }
        }
    }
}

// ---------------------------------------------------------------------------
extern "C" void kernel_launch(void* const* d_in, const int* in_sizes, int n_in,
                              void* d_out, int out_size)
{
    const float* x    = (const float*)d_in[0];
    const float* h0   = (const float*)d_in[1];
    const float* w_ih = (const float*)d_in[2];
    const float* w_hh = (const float*)d_in[3];
    const float* b_ih = (const float*)d_in[4];
    const float* b_hh = (const float*)d_in[5];
    const float* w1   = (const float*)d_in[6];
    const float* b1   = (const float*)d_in[7];
    const float* w2   = (const float*)d_in[8];
    const float* b2   = (const float*)d_in[9];
    const float* w3   = (const float*)d_in[10];
    const float* b3   = (const float*)d_in[11];
    float* out = (float*)d_out;

    cudaFuncSetAttribute(fused_persist,
                         cudaFuncAttributeMaxDynamicSharedMemorySize, FUSED_SMEM);

    fused_persist<<<GRID_P, 512, FUSED_SMEM>>>(h0, x, w_ih, w_hh, b_ih, b_hh,
                                               w1, b1, w2, b2, w3, b3, out);
}

// round 16
// speedup vs baseline: 1.6518x; 1.0219x over previous
#include <cuda_runtime.h>
#include <cuda_bf16.h>
#include <cuda_fp16.h>
#include <math.h>
#include <string.h>

typedef unsigned int u32;
typedef unsigned long long u64;

// ---------------------------------------------------------------------------
// Problem constants
// ---------------------------------------------------------------------------
constexpr int T    = 64;
constexpr int B    = 2048;
constexpr int H    = 256;
constexpr int H1   = 64;
constexpr int H2   = 64;
constexpr int OUTD = 601;
constexpr int RROWS = 64;
constexpr int NTILE = T * B / RROWS;      // 2048 MLP tiles
constexpr int NCOPY = 8;
constexpr int NTILE_TOT = NTILE + NCOPY;  // 2056

// ---------------------------------------------------------------------------
// PTX helpers
// ---------------------------------------------------------------------------
__device__ __forceinline__ u32 smem_u32(const void* p) {
    u32 a;
    asm("{ .reg .u64 t; cvta.to.shared.u64 t, %1; cvt.u32.u64 %0, t; }"
        : "=r"(a) : "l"(p));
    return a;
}
__device__ __forceinline__ void ldsm_x4(u32& r0, u32& r1, u32& r2, u32& r3, u32 addr) {
    asm volatile("ldmatrix.sync.aligned.m8n8.x4.shared.b16 {%0,%1,%2,%3}, [%4];"
                 : "=r"(r0), "=r"(r1), "=r"(r2), "=r"(r3) : "r"(addr));
}
__device__ __forceinline__ void mma_f16(float* d, const u32* a, const u32* b) {
    asm volatile(
        "mma.sync.aligned.m16n8k16.row.col.f32.f16.f16.f32 "
        "{%0,%1,%2,%3}, {%4,%5,%6,%7}, {%8,%9}, {%0,%1,%2,%3};"
        : "+f"(d[0]), "+f"(d[1]), "+f"(d[2]), "+f"(d[3])
        : "r"(a[0]), "r"(a[1]), "r"(a[2]), "r"(a[3]), "r"(b[0]), "r"(b[1]));
}
__device__ __forceinline__ void cp16(u32 dst, const void* src) {
    asm volatile("cp.async.ca.shared.global [%0], [%1], 16;" :: "r"(dst), "l"(src));
}
__device__ __forceinline__ void cp_commit() {
    asm volatile("cp.async.commit_group;" ::: "memory");
}
template <int N>
__device__ __forceinline__ void cp_wait_group() {
    asm volatile("cp.async.wait_group %0;" :: "n"(N) : "memory");
}
__device__ __forceinline__ u32 f2h2(float x, float y) {
    __half2 h = __floats2half2_rn(x, y);
    u32 r; memcpy(&r, &h, 4); return r;
}
__device__ __forceinline__ u64 ffma2(u64 a, u64 b, u64 c) {
    u64 d; asm("fma.rn.f32x2 %0, %1, %2, %3;" : "=l"(d) : "l"(a), "l"(b), "l"(c));
    return d;
}
__device__ __forceinline__ u64 pack2(float x, float y) {
    u64 d; asm("mov.b64 %0, {%1, %2};" : "=l"(d) : "f"(x), "f"(y));
    return d;
}
__device__ __forceinline__ float2 unpack2(u64 v) {
    float2 r; asm("mov.b64 {%0, %1}, %2;" : "=f"(r.x), "=f"(r.y) : "l"(v));
    return r;
}
constexpr float LOG2E = 1.4426950408889634f;
__device__ __forceinline__ float fast_sigmoid(float v) {
    float e; asm("ex2.approx.f32 %0, %1;" : "=f"(e) : "f"(-LOG2E * v));
    float r; asm("rcp.approx.f32 %0, %1;" : "=f"(r) : "f"(1.f + e));
    return r;
}
__device__ __forceinline__ float fast_tanh(float v) {
    float e; asm("ex2.approx.f32 %0, %1;" : "=f"(e) : "f"(2.f * LOG2E * v));
    float r; asm("rcp.approx.f32 %0, %1;" : "=f"(r) : "f"(1.f + e));
    return 1.f - 2.f * r;
}
__device__ __forceinline__ float fast_elu(float v) {
    if (v > 0.f) return v;
    float e; asm("ex2.approx.f32 %0, %1;" : "=f"(e) : "f"(LOG2E * v));
    return e - 1.f;
}

// ---------------------------------------------------------------------------
// Device scratch
// ---------------------------------------------------------------------------
__device__ float g_ys[(size_t)T * B * H];        // fp32 h (MLP input, h_last)
__device__ u32 g_hf16[(size_t)T * B * (H / 2)];  // fp16x2 h (sibling exchange)
__device__ u32 g_cnt[32 * 32] = {};              // per-bg monotonic counters
__device__ u32 g_q = 0;                          // work queue

// ---------------------------------------------------------------------------
// Single fused persistent kernel: 148 blocks x 512 threads.
// GRU (blocks 0..127): single fp16 HMMA, ALL 16 warps MMA (warp tile m16xn48),
// staging = pure cp.async from fp16 exchange array. Consumers: MLP + copy.
// ---------------------------------------------------------------------------
constexpr int GRID_P = 148;
constexpr int NGRU   = 128;
constexpr int SM_W   = 0;          // W fp16 [4 chunks][192 rows][128B] = 98304
constexpr int SM_A   = 98304;      // 4 bufs x 8192 (64 rows x 128B fp16)
constexpr int SM_PRM = 131072;     // 7*64 f32
constexpr int SM_Q   = 165376;     // queue slot
constexpr int FUSED_SMEM = 165504;

__device__ __forceinline__ void mma_sec16(float A[3][2][4], u32 ab, u32 wb,
                                          int wm, int wn,
                                          int a_row, int a_colh,
                                          int b_row, int b_colh)
{
    #pragma unroll
    for (int ks = 0; ks < 4; ks++) {
        u32 av[4];
        {
            int r = wm * 16 + a_row;
            u32 off = (u32)(r * 128) + (u32)((ks * 32 + a_colh) ^ ((r & 7) << 4));
            ldsm_x4(av[0], av[1], av[2], av[3], ab + off);
        }
        #pragma unroll
        for (int g = 0; g < 3; g++) {
            int rr = g * 64 + wn * 16 + b_row;
            u32 off = (u32)(rr * 128) + (u32)((ks * 32 + b_colh) ^ ((rr & 7) << 4));
            u32 bh[4];
            ldsm_x4(bh[0], bh[1], bh[2], bh[3], wb + off);
            mma_f16(A[g][0], av, bh);
            mma_f16(A[g][1], av, bh + 2);
        }
    }
}

__global__ void __launch_bounds__(512, 1)
fused_persist(const float* __restrict__ h0,
              const float* __restrict__ x,
              const float* __restrict__ w_ih,
              const float* __restrict__ w_hh,
              const float* __restrict__ b_ih,
              const float* __restrict__ b_hh,
              const float* __restrict__ w1, const float* __restrict__ b1,
              const float* __restrict__ w2, const float* __restrict__ b2,
              const float* __restrict__ w3, const float* __restrict__ b3,
              float* __restrict__ out)
{
    extern __shared__ char smem[];
    const u32 sb = smem_u32(smem);
    const int tid  = threadIdx.x;

    // =====================================================================
    // GRU producer part
    // =====================================================================
    if (blockIdx.x < NGRU) {
        float* sparam = (float*)(smem + SM_PRM);
        const int wid  = tid >> 5;
        const int lane = tid & 31;
        const int jc = blockIdx.x & 3;
        const int bg = blockIdx.x >> 2;
        const int j0 = jc * 64;
        const int b0 = bg * 64;
        const int wm = wid >> 2;    // 0..3 (16 rows each)
        const int wn = wid & 3;     // 0..3 (16 j-cols x 3 gates)
        const int l4 = lane >> 2;
        const int lp = lane & 3;

        if (tid < 64) {
            int jg = j0 + tid;
            sparam[tid]        = w_ih[jg];
            sparam[64 + tid]   = w_ih[H + jg];
            sparam[128 + tid]  = w_ih[2 * H + jg];
            sparam[192 + tid]  = b_ih[jg]         + b_hh[jg];
            sparam[256 + tid]  = b_ih[H + jg]     + b_hh[H + jg];
            sparam[320 + tid]  = b_ih[2 * H + jg];
            sparam[384 + tid]  = b_hh[2 * H + jg];
        }

        // W: fp32 -> fp16, SW128, resident: [c][rr=g*64+jj][128B]
        for (int c = 0; c < 4; c++) {
            for (int f = tid; f < 192 * 16; f += 512) {
                int rr = f >> 4, cc = f & 15;
                int g = rr >> 6, jj = rr & 63;
                float4 w = *(const float4*)&w_hh[((size_t)(g * H + j0 + jj)) * H
                                                 + c * 64 + cc * 4];
                u32 o = (u32)(c * 24576 + rr * 128) + (u32)((cc * 8) ^ ((rr & 7) << 4));
                *(u32*)(smem + SM_W + o)     = f2h2(w.x, w.y);
                *(u32*)(smem + SM_W + o + 4) = f2h2(w.z, w.w);
            }
        }

        const int a_row  = lane & 15;
        const int a_colh = (lane >> 4) * 16;
        const int b_row  = ((lane >> 4) << 3) + (lane & 7);
        const int b_colh = ((lane >> 3) & 1) * 16;

        // register h state: rows wm*16 + half*8 + l4; j = wn*16 + sub*8 + 2lp
        float2 hst[2][2];
        #pragma unroll
        for (int half = 0; half < 2; half++)
            #pragma unroll
            for (int sub = 0; sub < 2; sub++) {
                int rowg = b0 + wm * 16 + half * 8 + l4;
                int jl = wn * 16 + 8 * sub + 2 * lp;
                hst[half][sub] = *(const float2*)&h0[(size_t)rowg * H + j0 + jl];
            }

        // pre-stage OWN chunk (jc) of h0 as fp16 (4 u32 per thread)
        {
            int row = tid >> 3, kpl = (tid & 7) * 4;
            const float* src = &h0[(size_t)(b0 + row) * H + jc * 64 + kpl * 2];
            float4 wa = *(const float4*)src;
            float4 wb = *(const float4*)(src + 4);
            u32 off = (u32)(row * 128) + (u32)((kpl * 4) ^ ((row & 7) << 4));
            *(uint4*)(smem + SM_A + jc * 8192 + off) =
                make_uint4(f2h2(wa.x, wa.y), f2h2(wa.z, wa.w),
                           f2h2(wb.x, wb.y), f2h2(wb.z, wb.w));
        }
        __syncthreads();

        const int c1 = (jc + 1) & 3, c2 = (jc + 2) & 3, c3 = (jc + 3) & 3;
        const int cs[3] = {c1, c2, c3};

        for (int t = 0; t < T; t++) {
            float xvv[2];
            xvv[0] = x[(size_t)t * B + b0 + wm * 16 + l4];
            xvv[1] = x[(size_t)t * B + b0 + wm * 16 + 8 + l4];

            float A[3][2][4];
            #pragma unroll
            for (int g = 0; g < 3; g++)
                #pragma unroll
                for (int s = 0; s < 2; s++)
                    #pragma unroll
                    for (int q = 0; q < 4; q++) A[g][s][q] = 0.f;

            // own chunk first (no inter-block wait)
            mma_sec16(A, sb + SM_A + jc * 8192, sb + SM_W + jc * 24576,
                      wm, wn, a_row, a_colh, b_row, b_colh);

            // poll + stage sibling chunks
            if (t > 0) {
                if (tid == 0) {
                    u32 g;
                    do {
                        asm volatile("ld.acquire.gpu.global.u32 %0, [%1];"
                                     : "=r"(g) : "l"(&g_cnt[bg * 32]));
                    } while ((int)(g - (u32)(4 * t)) < 0);
                }
                __syncthreads();
                // 1 cp16 per thread per chunk
                int row = tid >> 3, cl = tid & 7;
                u32 doff = (u32)(row * 128) + (u32)((cl * 16) ^ ((row & 7) << 4));
                size_t sbase = ((size_t)(t - 1) * B + b0 + row) * 128;
                #pragma unroll
                for (int ci = 0; ci < 3; ci++) {
                    int c = cs[ci];
                    cp16(sb + SM_A + c * 8192 + doff, &g_hf16[sbase + c * 32 + cl * 4]);
                }
                cp_commit();
                cp_wait_group<0>();
            } else {
                int row = tid >> 3, kpl = (tid & 7) * 4;
                u32 doff = (u32)(row * 128) + (u32)((kpl * 4) ^ ((row & 7) << 4));
                #pragma unroll
                for (int ci = 0; ci < 3; ci++) {
                    int c = cs[ci];
                    const float* src = &h0[(size_t)(b0 + row) * H + c * 64 + kpl * 2];
                    float4 wa = *(const float4*)src;
                    float4 wb = *(const float4*)(src + 4);
                    *(uint4*)(smem + SM_A + c * 8192 + doff) =
                        make_uint4(f2h2(wa.x, wa.y), f2h2(wa.z, wa.w),
                                   f2h2(wb.x, wb.y), f2h2(wb.z, wb.w));
                }
            }
            __syncthreads();

            // unbroken c1..c3 MMA
            mma_sec16(A, sb + SM_A + c1 * 8192, sb + SM_W + c1 * 24576,
                      wm, wn, a_row, a_colh, b_row, b_colh);
            mma_sec16(A, sb + SM_A + c2 * 8192, sb + SM_W + c2 * 24576,
                      wm, wn, a_row, a_colh, b_row, b_colh);
            mma_sec16(A, sb + SM_A + c3 * 8192, sb + SM_W + c3 * 24576,
                      wm, wn, a_row, a_colh, b_row, b_colh);
            __syncthreads();   // all warps done reading A bufs

            // epilogue: 8 gate computations per lane
            float* yrow = g_ys + (size_t)t * B * H;
            #pragma unroll
            for (int half = 0; half < 2; half++) {
                int rowl = wm * 16 + half * 8 + l4;
                int rowg = b0 + rowl;
                float xv = xvv[half];
                #pragma unroll
                for (int sub = 0; sub < 2; sub++) {
                    int jl = wn * 16 + 8 * sub + 2 * lp;
                    float hn0, hn1;
                    {
                        int j = jl;
                        float r = fast_sigmoid(xv * sparam[j] + sparam[192 + j]
                                               + A[0][sub][half * 2]);
                        float z = fast_sigmoid(xv * sparam[64 + j] + sparam[256 + j]
                                               + A[1][sub][half * 2]);
                        float n = fast_tanh(xv * sparam[128 + j] + sparam[320 + j]
                                            + r * (A[2][sub][half * 2] + sparam[384 + j]));
                        hn0 = (1.f - z) * n + z * hst[half][sub].x;
                    }
                    {
                        int j = jl + 1;
                        float r = fast_sigmoid(xv * sparam[j] + sparam[192 + j]
                                               + A[0][sub][half * 2 + 1]);
                        float z = fast_sigmoid(xv * sparam[64 + j] + sparam[256 + j]
                                               + A[1][sub][half * 2 + 1]);
                        float n = fast_tanh(xv * sparam[128 + j] + sparam[320 + j]
                                            + r * (A[2][sub][half * 2 + 1] + sparam[384 + j]));
                        hn1 = (1.f - z) * n + z * hst[half][sub].y;
                    }
                    hst[half][sub] = make_float2(hn0, hn1);

                    // fp32 for MLP consumers
                    *(float2*)&yrow[(size_t)rowg * H + j0 + jl] = hst[half][sub];
                    // fp16 for sibling exchange
                    int kp = wn * 8 + 4 * sub + lp;
                    u32 uh = f2h2(hn0, hn1);
                    g_hf16[((size_t)t * B + rowg) * 128 + jc * 32 + kp] = uh;
                    // own chunk fp16 into buf[jc] for next step
                    u32 off = (u32)(rowl * 128) + (u32)((kp * 4) ^ ((rowl & 7) << 4));
                    *(u32*)(smem + SM_A + jc * 8192 + off) = uh;
                }
            }

            __threadfence();
            __syncthreads();
            if (tid == 0) atomicAdd(&g_cnt[bg * 32], 1u);
        }
        __syncthreads();
    }

    // =====================================================================
    // Consumer part (all blocks): MLP tiles + h_last copy tiles
    // =====================================================================
    {
        float* sm  = (float*)smem;
        float* xt  = sm;            // [64][256]
        float* w1s = sm + 16384;    // [64][260]
        float* h1s = sm + 33024;    // [64][64]
        float* h2t = sm + 37120;    // [64][66]
        float* w3s = sm;            // alias xt
        float* w2s = sm + 16384;    // alias w1s
        u32* qs = (u32*)(smem + SM_Q);

        const int jp = tid & 31;
        const int rg = (tid >> 5) & 7;
        const bool act = tid < 256;

        for (;;) {
            __syncthreads();
            if (tid == 0) *qs = atomicAdd(&g_q, 1u);
            __syncthreads();
            u32 q = *qs;
            if (q >= (u32)NTILE_TOT) {
                if (q == (u32)(NTILE_TOT + GRID_P - 1) && tid == 0) {
                    for (int i = 0; i < 32; i++) g_cnt[i * 32] = 0;
                    __threadfence();
                    atomicExch(&g_q, 0u);
                }
                break;
            }

            if (q >= (u32)NTILE) {
                // h_last copy tile: 256 rows, gated on 4 bgs complete
                int seg = (int)(q - NTILE);
                if (tid < 4) {
                    u32 g;
                    do {
                        asm volatile("ld.acquire.gpu.global.u32 %0, [%1];"
                                     : "=r"(g) : "l"(&g_cnt[(seg * 4 + tid) * 32]));
                    } while ((int)(g - (u32)(4 * T)) < 0);
                }
                __syncthreads();
                const float4* src = (const float4*)
                    (g_ys + ((size_t)(T - 1) * B + (size_t)seg * 256) * H);
                float4* dst = (float4*)
                    (out + (size_t)T * B * OUTD + (size_t)seg * 256 * H);
                for (int i = tid; i < 256 * H / 4; i += 512) dst[i] = src[i];
                continue;
            }

            int tt  = (int)(q >> 5);
            int bgq = (int)(q & 31);

            if (tid == 0) {
                u32 target = (u32)(4 * (tt + 1)), g;
                do {
                    asm volatile("ld.acquire.gpu.global.u32 %0, [%1];"
                                 : "=r"(g) : "l"(&g_cnt[bgq * 32]));
                } while ((int)(g - target) < 0);
            }
            __syncthreads();

            const size_t row0 = (size_t)q * RROWS;

            {
                const float4* src = (const float4*)(g_ys + row0 * H);
                float4* dst = (float4*)xt;
                for (int i = tid; i < RROWS * H / 4; i += 512) dst[i] = src[i];
            }
            for (int f = tid; f < H * H1; f += 512) {
                int jj = f & 63; int k = f >> 6;
                w1s[jj * 260 + k] = w1[f];
            }
            __syncthreads();

            // Stage 1
            if (act) {
                float acc[8][2];
                #pragma unroll
                for (int i = 0; i < 8; i++) { acc[i][0] = 0.f; acc[i][1] = 0.f; }
                #pragma unroll 4
                for (int k = 0; k < H; k += 4) {
                    float4 wa = *(const float4*)&w1s[(2 * jp) * 260 + k];
                    float4 wb = *(const float4*)&w1s[(2 * jp + 1) * 260 + k];
                    #pragma unroll
                    for (int i = 0; i < 8; i++) {
                        float4 xv = *(const float4*)&xt[(rg * 8 + i) * H + k];
                        acc[i][0] += xv.x * wa.x + xv.y * wa.y + xv.z * wa.z + xv.w * wa.w;
                        acc[i][1] += xv.x * wb.x + xv.y * wb.y + xv.z * wb.z + xv.w * wb.w;
                    }
                }
                float ba = b1[2 * jp], bb = b1[2 * jp + 1];
                #pragma unroll
                for (int i = 0; i < 8; i++) {
                    h1s[(rg * 8 + i) * 64 + 2 * jp]     = fast_elu(acc[i][0] + ba);
                    h1s[(rg * 8 + i) * 64 + 2 * jp + 1] = fast_elu(acc[i][1] + bb);
                }
            }
            __syncthreads();

            for (int f = tid; f < H1 * H2; f += 512) {
                int jj = f & 63; int k = f >> 6;
                w2s[jj * 68 + k] = w2[f];
            }
            __syncthreads();

            // Stage 2 (h2 transposed)
            if (act) {
                float acc[8][2];
                #pragma unroll
                for (int i = 0; i < 8; i++) { acc[i][0] = 0.f; acc[i][1] = 0.f; }
                #pragma unroll
                for (int k = 0; k < H1; k += 4) {
                    float4 wa = *(const float4*)&w2s[(2 * jp) * 68 + k];
                    float4 wb = *(const float4*)&w2s[(2 * jp + 1) * 68 + k];
                    #pragma unroll
                    for (int i = 0; i < 8; i++) {
                        float4 xv = *(const float4*)&h1s[(rg * 8 + i) * 64 + k];
                        acc[i][0] += xv.x * wa.x + xv.y * wa.y + xv.z * wa.z + xv.w * wa.w;
                        acc[i][1] += xv.x * wb.x + xv.y * wb.y + xv.z * wb.z + xv.w * wb.w;
                    }
                }
                float ba = b2[2 * jp], bb = b2[2 * jp + 1];
                #pragma unroll
                for (int i = 0; i < 8; i++) {
                    int row = rg * 8 + i;
                    h2t[(2 * jp) * 66 + row]     = fast_elu(acc[i][0] + ba);
                    h2t[(2 * jp + 1) * 66 + row] = fast_elu(acc[i][1] + bb);
                }
            }
            __syncthreads();

            // Stage 3: packed fp32x2 over row pairs
            for (int c0 = 0; c0 < OUTD; c0 += 128) {
                for (int f = tid; f < 64 * 128; f += 512) {
                    int c = f & 127; int k = f >> 7;
                    int cg = c0 + c;
                    w3s[k * 128 + c] = (cg < OUTD) ? w3[(size_t)k * OUTD + cg] : 0.f;
                }
                __syncthreads();

                if (act) {
                    u64 acc[4][4];
                    #pragma unroll
                    for (int rp = 0; rp < 4; rp++)
                        #pragma unroll
                        for (int qq = 0; qq < 4; qq++) acc[rp][qq] = 0ull;

                    #pragma unroll 4
                    for (int k = 0; k < H2; k++) {
                        u64 wd[4];
                        #pragma unroll
                        for (int qq = 0; qq < 4; qq++) {
                            float w = w3s[k * 128 + jp + 32 * qq];
                            wd[qq] = pack2(w, w);
                        }
                        const float* hp = &h2t[k * 66 + rg * 8];
                        u64 hv0 = *(const u64*)(hp + 0);
                        u64 hv1 = *(const u64*)(hp + 2);
                        u64 hv2 = *(const u64*)(hp + 4);
                        u64 hv3 = *(const u64*)(hp + 6);
                        #pragma unroll
                        for (int qq = 0; qq < 4; qq++) {
                            acc[0][qq] = ffma2(hv0, wd[qq], acc[0][qq]);
                            acc[1][qq] = ffma2(hv1, wd[qq], acc[1][qq]);
                            acc[2][qq] = ffma2(hv2, wd[qq], acc[2][qq]);
                            acc[3][qq] = ffma2(hv3, wd[qq], acc[3][qq]);
                        }
                    }

                    #pragma unroll
                    for (int qq = 0; qq < 4; qq++) {
                        int cg = c0 + jp + 32 * qq;
                        if (cg < OUTD) {
                            float bq = b3[cg];
                            #pragma unroll
                            for (int rp = 0; rp < 4; rp++) {
                                float2 v = unpack2(acc[rp][qq]);
                                size_t row = row0 + rg * 8 + 2 * rp;
                                out[row * OUTD + cg]       = v.x + bq;
                                out[(row + 1) * OUTD + cg] = v.y + bq;
                            }
                        }
                    }
                }
                __syncthreads();
            }
        }
    }
}

// ---------------------------------------------------------------------------
extern "C" void kernel_launch(void* const* d_in, const int* in_sizes, int n_in,
                              void* d_out, int out_size)
{
    const float* x    = (const float*)d_in[0];
    const float* h0   = (const float*)d_in[1];
    const float* w_ih = (const float*)d_in[2];
    const float* w_hh = (const float*)d_in[3];
    const float* b_ih = (const float*)d_in[4];
    const float* b_hh = (const float*)d_in[5];
    const float* w1   = (const float*)d_in[6];
    const float* b1   = (const float*)d_in[7];
    const float* w2   = (const float*)d_in[8];
    const float* b2   = (const float*)d_in[9];
    const float* w3   = (const float*)d_in[10];
    const float* b3   = (const float*)d_in[11];
    float* out = (float*)d_out;

    cudaFuncSetAttribute(fused_persist,
                         cudaFuncAttributeMaxDynamicSharedMemorySize, FUSED_SMEM);

    fused_persist<<<GRID_P, 512, FUSED_SMEM>>>(h0, x, w_ih, w_hh, b_ih, b_hh,
                                               w1, b1, w2, b2, w3, b3, out);
}

// round 17
// speedup vs baseline: 1.7268x; 1.0454x over previous
#include <cuda_runtime.h>
#include <cuda_bf16.h>
#include <cuda_fp16.h>
#include <math.h>
#include <string.h>

typedef unsigned int u32;
typedef unsigned long long u64;

// ---------------------------------------------------------------------------
// Problem constants
// ---------------------------------------------------------------------------
constexpr int T    = 64;
constexpr int B    = 2048;
constexpr int H    = 256;
constexpr int H1   = 64;
constexpr int H2   = 64;
constexpr int OUTD = 601;
constexpr int RROWS = 64;
constexpr int NTILE = T * B / RROWS;      // 2048 MLP tiles
constexpr int NCOPY = 8;
constexpr int NTILE_TOT = NTILE + NCOPY;  // 2056

// ---------------------------------------------------------------------------
// PTX helpers
// ---------------------------------------------------------------------------
__device__ __forceinline__ u32 smem_u32(const void* p) {
    u32 a;
    asm("{ .reg .u64 t; cvta.to.shared.u64 t, %1; cvt.u32.u64 %0, t; }"
        : "=r"(a) : "l"(p));
    return a;
}
__device__ __forceinline__ void ldsm_x4(u32& r0, u32& r1, u32& r2, u32& r3, u32 addr) {
    asm volatile("ldmatrix.sync.aligned.m8n8.x4.shared.b16 {%0,%1,%2,%3}, [%4];"
                 : "=r"(r0), "=r"(r1), "=r"(r2), "=r"(r3) : "r"(addr));
}
__device__ __forceinline__ void mma_f16(float* d, const u32* a, const u32* b) {
    asm volatile(
        "mma.sync.aligned.m16n8k16.row.col.f32.f16.f16.f32 "
        "{%0,%1,%2,%3}, {%4,%5,%6,%7}, {%8,%9}, {%0,%1,%2,%3};"
        : "+f"(d[0]), "+f"(d[1]), "+f"(d[2]), "+f"(d[3])
        : "r"(a[0]), "r"(a[1]), "r"(a[2]), "r"(a[3]), "r"(b[0]), "r"(b[1]));
}
__device__ __forceinline__ void cp16(u32 dst, const void* src) {
    asm volatile("cp.async.ca.shared.global [%0], [%1], 16;" :: "r"(dst), "l"(src));
}
__device__ __forceinline__ void cp_commit() {
    asm volatile("cp.async.commit_group;" ::: "memory");
}
template <int N>
__device__ __forceinline__ void cp_wait_group() {
    asm volatile("cp.async.wait_group %0;" :: "n"(N) : "memory");
}
__device__ __forceinline__ u32 f2h2(float x, float y) {
    __half2 h = __floats2half2_rn(x, y);
    u32 r; memcpy(&r, &h, 4); return r;
}
__device__ __forceinline__ float2 h2f2(u32 v) {
    __half2 h; memcpy(&h, &v, 4);
    return __half22float2(h);
}
__device__ __forceinline__ u64 ffma2(u64 a, u64 b, u64 c) {
    u64 d; asm("fma.rn.f32x2 %0, %1, %2, %3;" : "=l"(d) : "l"(a), "l"(b), "l"(c));
    return d;
}
__device__ __forceinline__ u64 pack2(float x, float y) {
    u64 d; asm("mov.b64 %0, {%1, %2};" : "=l"(d) : "f"(x), "f"(y));
    return d;
}
__device__ __forceinline__ float2 unpack2(u64 v) {
    float2 r; asm("mov.b64 {%0, %1}, %2;" : "=f"(r.x), "=f"(r.y) : "l"(v));
    return r;
}
constexpr float LOG2E = 1.4426950408889634f;
__device__ __forceinline__ float fast_sigmoid(float v) {
    float e; asm("ex2.approx.f32 %0, %1;" : "=f"(e) : "f"(-LOG2E * v));
    float r; asm("rcp.approx.f32 %0, %1;" : "=f"(r) : "f"(1.f + e));
    return r;
}
__device__ __forceinline__ float fast_tanh(float v) {
    float e; asm("ex2.approx.f32 %0, %1;" : "=f"(e) : "f"(2.f * LOG2E * v));
    float r; asm("rcp.approx.f32 %0, %1;" : "=f"(r) : "f"(1.f + e));
    return 1.f - 2.f * r;
}
__device__ __forceinline__ float fast_elu(float v) {
    if (v > 0.f) return v;
    float e; asm("ex2.approx.f32 %0, %1;" : "=f"(e) : "f"(LOG2E * v));
    return e - 1.f;
}

// ---------------------------------------------------------------------------
// Device scratch: h stored ONLY as t-indexed fp16x2 (exchange + MLP input)
// ---------------------------------------------------------------------------
__device__ u32 g_hf16[(size_t)T * B * (H / 2)];
__device__ u32 g_cnt[32 * 32] = {};
__device__ u32 g_q = 0;

// ---------------------------------------------------------------------------
// Single fused persistent kernel: 148 blocks x 512 threads.
// ---------------------------------------------------------------------------
constexpr int GRID_P = 148;
constexpr int NGRU   = 128;
constexpr int SM_W   = 0;          // W fp16 [4 chunks][192 rows][128B] = 98304
constexpr int SM_A   = 98304;      // 4 bufs x 8192 (64 rows x 128B fp16)
constexpr int SM_PRM = 131072;     // 7*64 f32
constexpr int SM_Q   = 165376;     // queue slot
constexpr int FUSED_SMEM = 165504;

__device__ __forceinline__ void mma_sec16(float A[3][2][4], u32 ab, u32 wb,
                                          int wm, int wn,
                                          int a_row, int a_colh,
                                          int b_row, int b_colh)
{
    #pragma unroll
    for (int ks = 0; ks < 4; ks++) {
        u32 av[4];
        {
            int r = wm * 16 + a_row;
            u32 off = (u32)(r * 128) + (u32)((ks * 32 + a_colh) ^ ((r & 7) << 4));
            ldsm_x4(av[0], av[1], av[2], av[3], ab + off);
        }
        #pragma unroll
        for (int g = 0; g < 3; g++) {
            int rr = g * 64 + wn * 16 + b_row;
            u32 off = (u32)(rr * 128) + (u32)((ks * 32 + b_colh) ^ ((rr & 7) << 4));
            u32 bh[4];
            ldsm_x4(bh[0], bh[1], bh[2], bh[3], wb + off);
            mma_f16(A[g][0], av, bh);
            mma_f16(A[g][1], av, bh + 2);
        }
    }
}

__global__ void __launch_bounds__(512, 1)
fused_persist(const float* __restrict__ h0,
              const float* __restrict__ x,
              const float* __restrict__ w_ih,
              const float* __restrict__ w_hh,
              const float* __restrict__ b_ih,
              const float* __restrict__ b_hh,
              const float* __restrict__ w1, const float* __restrict__ b1,
              const float* __restrict__ w2, const float* __restrict__ b2,
              const float* __restrict__ w3, const float* __restrict__ b3,
              float* __restrict__ out)
{
    extern __shared__ char smem[];
    const u32 sb = smem_u32(smem);
    const int tid  = threadIdx.x;

    // =====================================================================
    // GRU producer part
    // =====================================================================
    if (blockIdx.x < NGRU) {
        float* sparam = (float*)(smem + SM_PRM);
        const int wid  = tid >> 5;
        const int lane = tid & 31;
        const int jc = blockIdx.x & 3;
        const int bg = blockIdx.x >> 2;
        const int j0 = jc * 64;
        const int b0 = bg * 64;
        const int wm = wid >> 2;
        const int wn = wid & 3;
        const int l4 = lane >> 2;
        const int lp = lane & 3;

        if (tid < 64) {
            int jg = j0 + tid;
            sparam[tid]        = w_ih[jg];
            sparam[64 + tid]   = w_ih[H + jg];
            sparam[128 + tid]  = w_ih[2 * H + jg];
            sparam[192 + tid]  = b_ih[jg]         + b_hh[jg];
            sparam[256 + tid]  = b_ih[H + jg]     + b_hh[H + jg];
            sparam[320 + tid]  = b_ih[2 * H + jg];
            sparam[384 + tid]  = b_hh[2 * H + jg];
        }

        // W: fp32 -> fp16, SW128, resident
        for (int c = 0; c < 4; c++) {
            for (int f = tid; f < 192 * 16; f += 512) {
                int rr = f >> 4, cc = f & 15;
                int g = rr >> 6, jj = rr & 63;
                float4 w = *(const float4*)&w_hh[((size_t)(g * H + j0 + jj)) * H
                                                 + c * 64 + cc * 4];
                u32 o = (u32)(c * 24576 + rr * 128) + (u32)((cc * 8) ^ ((rr & 7) << 4));
                *(u32*)(smem + SM_W + o)     = f2h2(w.x, w.y);
                *(u32*)(smem + SM_W + o + 4) = f2h2(w.z, w.w);
            }
        }

        const int a_row  = lane & 15;
        const int a_colh = (lane >> 4) * 16;
        const int b_row  = ((lane >> 4) << 3) + (lane & 7);
        const int b_colh = ((lane >> 3) & 1) * 16;

        float2 hst[2][2];
        #pragma unroll
        for (int half = 0; half < 2; half++)
            #pragma unroll
            for (int sub = 0; sub < 2; sub++) {
                int rowg = b0 + wm * 16 + half * 8 + l4;
                int jl = wn * 16 + 8 * sub + 2 * lp;
                hst[half][sub] = *(const float2*)&h0[(size_t)rowg * H + j0 + jl];
            }

        // pre-stage OWN chunk (jc) of h0 as fp16
        {
            int row = tid >> 3, kpl = (tid & 7) * 4;
            const float* src = &h0[(size_t)(b0 + row) * H + jc * 64 + kpl * 2];
            float4 wa = *(const float4*)src;
            float4 wb = *(const float4*)(src + 4);
            u32 off = (u32)(row * 128) + (u32)((kpl * 4) ^ ((row & 7) << 4));
            *(uint4*)(smem + SM_A + jc * 8192 + off) =
                make_uint4(f2h2(wa.x, wa.y), f2h2(wa.z, wa.w),
                           f2h2(wb.x, wb.y), f2h2(wb.z, wb.w));
        }
        __syncthreads();

        const int c1 = (jc + 1) & 3, c2 = (jc + 2) & 3, c3 = (jc + 3) & 3;
        const int cs[3] = {c1, c2, c3};

        for (int t = 0; t < T; t++) {
            float xvv[2];
            xvv[0] = x[(size_t)t * B + b0 + wm * 16 + l4];
            xvv[1] = x[(size_t)t * B + b0 + wm * 16 + 8 + l4];

            float A[3][2][4];
            #pragma unroll
            for (int g = 0; g < 3; g++)
                #pragma unroll
                for (int s = 0; s < 2; s++)
                    #pragma unroll
                    for (int q = 0; q < 4; q++) A[g][s][q] = 0.f;

            // poll FIRST on tid0 (overlaps with own-chunk MMA of other warps)
            if (t > 0 && tid == 0) {
                u32 g;
                do {
                    asm volatile("ld.acquire.gpu.global.u32 %0, [%1];"
                                 : "=r"(g) : "l"(&g_cnt[bg * 32]));
                } while ((int)(g - (u32)(4 * t)) < 0);
            }

            // own chunk (no inter-block dependency)
            mma_sec16(A, sb + SM_A + jc * 8192, sb + SM_W + jc * 24576,
                      wm, wn, a_row, a_colh, b_row, b_colh);
            __syncthreads();   // poll done + all own-MMA reads of buf[jc] done

            // stage sibling chunks
            if (t > 0) {
                int row = tid >> 3, cl = tid & 7;
                u32 doff = (u32)(row * 128) + (u32)((cl * 16) ^ ((row & 7) << 4));
                size_t sbase = ((size_t)(t - 1) * B + b0 + row) * 128;
                #pragma unroll
                for (int ci = 0; ci < 3; ci++) {
                    int c = cs[ci];
                    cp16(sb + SM_A + c * 8192 + doff, &g_hf16[sbase + c * 32 + cl * 4]);
                }
                cp_commit();
                cp_wait_group<0>();
            } else {
                int row = tid >> 3, kpl = (tid & 7) * 4;
                u32 doff = (u32)(row * 128) + (u32)((kpl * 4) ^ ((row & 7) << 4));
                #pragma unroll
                for (int ci = 0; ci < 3; ci++) {
                    int c = cs[ci];
                    const float* src = &h0[(size_t)(b0 + row) * H + c * 64 + kpl * 2];
                    float4 wa = *(const float4*)src;
                    float4 wb = *(const float4*)(src + 4);
                    *(uint4*)(smem + SM_A + c * 8192 + doff) =
                        make_uint4(f2h2(wa.x, wa.y), f2h2(wa.z, wa.w),
                                   f2h2(wb.x, wb.y), f2h2(wb.z, wb.w));
                }
            }
            __syncthreads();

            // unbroken c1..c3 MMA (no sync after: epilogue only writes buf[jc],
            // whose reads all completed before the first sync)
            mma_sec16(A, sb + SM_A + c1 * 8192, sb + SM_W + c1 * 24576,
                      wm, wn, a_row, a_colh, b_row, b_colh);
            mma_sec16(A, sb + SM_A + c2 * 8192, sb + SM_W + c2 * 24576,
                      wm, wn, a_row, a_colh, b_row, b_colh);
            mma_sec16(A, sb + SM_A + c3 * 8192, sb + SM_W + c3 * 24576,
                      wm, wn, a_row, a_colh, b_row, b_colh);

            // epilogue: gates; fp16 stores only (16KB/block)
            #pragma unroll
            for (int half = 0; half < 2; half++) {
                int rowl = wm * 16 + half * 8 + l4;
                int rowg = b0 + rowl;
                float xv = xvv[half];
                #pragma unroll
                for (int sub = 0; sub < 2; sub++) {
                    int jl = wn * 16 + 8 * sub + 2 * lp;
                    float hn0, hn1;
                    {
                        int j = jl;
                        float r = fast_sigmoid(xv * sparam[j] + sparam[192 + j]
                                               + A[0][sub][half * 2]);
                        float z = fast_sigmoid(xv * sparam[64 + j] + sparam[256 + j]
                                               + A[1][sub][half * 2]);
                        float n = fast_tanh(xv * sparam[128 + j] + sparam[320 + j]
                                            + r * (A[2][sub][half * 2] + sparam[384 + j]));
                        hn0 = (1.f - z) * n + z * hst[half][sub].x;
                    }
                    {
                        int j = jl + 1;
                        float r = fast_sigmoid(xv * sparam[j] + sparam[192 + j]
                                               + A[0][sub][half * 2 + 1]);
                        float z = fast_sigmoid(xv * sparam[64 + j] + sparam[256 + j]
                                               + A[1][sub][half * 2 + 1]);
                        float n = fast_tanh(xv * sparam[128 + j] + sparam[320 + j]
                                            + r * (A[2][sub][half * 2 + 1] + sparam[384 + j]));
                        hn1 = (1.f - z) * n + z * hst[half][sub].y;
                    }
                    hst[half][sub] = make_float2(hn0, hn1);

                    int kp = wn * 8 + 4 * sub + lp;
                    u32 uh = f2h2(hn0, hn1);
                    g_hf16[((size_t)t * B + rowg) * 128 + jc * 32 + kp] = uh;
                    u32 off = (u32)(rowl * 128) + (u32)((kp * 4) ^ ((rowl & 7) << 4));
                    *(u32*)(smem + SM_A + jc * 8192 + off) = uh;
                }
            }

            __threadfence();
            __syncthreads();
            if (tid == 0) atomicAdd(&g_cnt[bg * 32], 1u);
        }
        __syncthreads();
    }

    // =====================================================================
    // Consumer part (all blocks): MLP tiles + h_last copy tiles
    // =====================================================================
    {
        float* sm  = (float*)smem;
        float* xt  = sm;            // [64][256]
        float* w1s = sm + 16384;    // [64][260]
        float* h1s = sm + 33024;    // [64][64]
        float* h2t = sm + 37120;    // [64][66]
        float* w3s = sm;            // alias xt
        float* w2s = sm + 16384;    // alias w1s
        u32* qs = (u32*)(smem + SM_Q);

        const int jp = tid & 31;
        const int rg = (tid >> 5) & 7;
        const bool act = tid < 256;

        for (;;) {
            __syncthreads();
            if (tid == 0) *qs = atomicAdd(&g_q, 1u);
            __syncthreads();
            u32 q = *qs;
            if (q >= (u32)NTILE_TOT) {
                if (q == (u32)(NTILE_TOT + GRID_P - 1) && tid == 0) {
                    for (int i = 0; i < 32; i++) g_cnt[i * 32] = 0;
                    __threadfence();
                    atomicExch(&g_q, 0u);
                }
                break;
            }

            if (q >= (u32)NTILE) {
                // h_last copy tile: reconstruct fp32 from fp16
                int seg = (int)(q - NTILE);
                if (tid < 4) {
                    u32 g;
                    do {
                        asm volatile("ld.acquire.gpu.global.u32 %0, [%1];"
                                     : "=r"(g) : "l"(&g_cnt[(seg * 4 + tid) * 32]));
                    } while ((int)(g - (u32)(4 * T)) < 0);
                }
                __syncthreads();
                size_t base = ((size_t)(T - 1) * B + (size_t)seg * 256) * 128;
                float* dst = out + (size_t)T * B * OUTD + (size_t)seg * 256 * H;
                for (int i = tid; i < 256 * 128; i += 512) {
                    *(float2*)&dst[2 * i] = h2f2(g_hf16[base + i]);
                }
                continue;
            }

            int tt  = (int)(q >> 5);
            int bgq = (int)(q & 31);

            if (tid == 0) {
                u32 target = (u32)(4 * (tt + 1)), g;
                do {
                    asm volatile("ld.acquire.gpu.global.u32 %0, [%1];"
                                 : "=r"(g) : "l"(&g_cnt[bgq * 32]));
                } while ((int)(g - target) < 0);
            }
            __syncthreads();

            const size_t row0 = (size_t)q * RROWS;

            // reconstruct xt fp32 from fp16
            {
                const u32* hh = g_hf16 + row0 * 128;
                for (int i = tid; i < RROWS * 128; i += 512) {
                    int row = i >> 7, kp = i & 127;
                    *(float2*)&xt[row * 256 + 2 * kp] = h2f2(hh[i]);
                }
            }
            for (int f = tid; f < H * H1; f += 512) {
                int jj = f & 63; int k = f >> 6;
                w1s[jj * 260 + k] = w1[f];
            }
            __syncthreads();

            // Stage 1
            if (act) {
                float acc[8][2];
                #pragma unroll
                for (int i = 0; i < 8; i++) { acc[i][0] = 0.f; acc[i][1] = 0.f; }
                #pragma unroll 4
                for (int k = 0; k < H; k += 4) {
                    float4 wa = *(const float4*)&w1s[(2 * jp) * 260 + k];
                    float4 wb = *(const float4*)&w1s[(2 * jp + 1) * 260 + k];
                    #pragma unroll
                    for (int i = 0; i < 8; i++) {
                        float4 xv = *(const float4*)&xt[(rg * 8 + i) * H + k];
                        acc[i][0] += xv.x * wa.x + xv.y * wa.y + xv.z * wa.z + xv.w * wa.w;
                        acc[i][1] += xv.x * wb.x + xv.y * wb.y + xv.z * wb.z + xv.w * wb.w;
                    }
                }
                float ba = b1[2 * jp], bb = b1[2 * jp + 1];
                #pragma unroll
                for (int i = 0; i < 8; i++) {
                    h1s[(rg * 8 + i) * 64 + 2 * jp]     = fast_elu(acc[i][0] + ba);
                    h1s[(rg * 8 + i) * 64 + 2 * jp + 1] = fast_elu(acc[i][1] + bb);
                }
            }
            __syncthreads();

            for (int f = tid; f < H1 * H2; f += 512) {
                int jj = f & 63; int k = f >> 6;
                w2s[jj * 68 + k] = w2[f];
            }
            __syncthreads();

            // Stage 2 (h2 transposed)
            if (act) {
                float acc[8][2];
                #pragma unroll
                for (int i = 0; i < 8; i++) { acc[i][0] = 0.f; acc[i][1] = 0.f; }
                #pragma unroll
                for (int k = 0; k < H1; k += 4) {
                    float4 wa = *(const float4*)&w2s[(2 * jp) * 68 + k];
                    float4 wb = *(const float4*)&w2s[(2 * jp + 1) * 68 + k];
                    #pragma unroll
                    for (int i = 0; i < 8; i++) {
                        float4 xv = *(const float4*)&h1s[(rg * 8 + i) * 64 + k];
                        acc[i][0] += xv.x * wa.x + xv.y * wa.y + xv.z * wa.z + xv.w * wa.w;
                        acc[i][1] += xv.x * wb.x + xv.y * wb.y + xv.z * wb.z + xv.w * wb.w;
                    }
                }
                float ba = b2[2 * jp], bb = b2[2 * jp + 1];
                #pragma unroll
                for (int i = 0; i < 8; i++) {
                    int row = rg * 8 + i;
                    h2t[(2 * jp) * 66 + row]     = fast_elu(acc[i][0] + ba);
                    h2t[(2 * jp + 1) * 66 + row] = fast_elu(acc[i][1] + bb);
                }
            }
            __syncthreads();

            // Stage 3: packed fp32x2 over row pairs
            for (int c0 = 0; c0 < OUTD; c0 += 128) {
                for (int f = tid; f < 64 * 128; f += 512) {
                    int c = f & 127; int k = f >> 7;
                    int cg = c0 + c;
                    w3s[k * 128 + c] = (cg < OUTD) ? w3[(size_t)k * OUTD + cg] : 0.f;
                }
                __syncthreads();

                if (act) {
                    u64 acc[4][4];
                    #pragma unroll
                    for (int rp = 0; rp < 4; rp++)
                        #pragma unroll
                        for (int qq = 0; qq < 4; qq++) acc[rp][qq] = 0ull;

                    #pragma unroll 4
                    for (int k = 0; k < H2; k++) {
                        u64 wd[4];
                        #pragma unroll
                        for (int qq = 0; qq < 4; qq++) {
                            float w = w3s[k * 128 + jp + 32 * qq];
                            wd[qq] = pack2(w, w);
                        }
                        const float* hp = &h2t[k * 66 + rg * 8];
                        u64 hv0 = *(const u64*)(hp + 0);
                        u64 hv1 = *(const u64*)(hp + 2);
                        u64 hv2 = *(const u64*)(hp + 4);
                        u64 hv3 = *(const u64*)(hp + 6);
                        #pragma unroll
                        for (int qq = 0; qq < 4; qq++) {
                            acc[0][qq] = ffma2(hv0, wd[qq], acc[0][qq]);
                            acc[1][qq] = ffma2(hv1, wd[qq], acc[1][qq]);
                            acc[2][qq] = ffma2(hv2, wd[qq], acc[2][qq]);
                            acc[3][qq] = ffma2(hv3, wd[qq], acc[3][qq]);
                        }
                    }

                    #pragma unroll
                    for (int qq = 0; qq < 4; qq++) {
                        int cg = c0 + jp + 32 * qq;
                        if (cg < OUTD) {
                            float bq = b3[cg];
                            #pragma unroll
                            for (int rp = 0; rp < 4; rp++) {
                                float2 v = unpack2(acc[rp][qq]);
                                size_t row = row0 + rg * 8 + 2 * rp;
                                out[row * OUTD + cg]       = v.x + bq;
                                out[(row + 1) * OUTD + cg] = v.y + bq;
                            }
                        }
                    }
                }
                __syncthreads();
            }
        }
    }
}

// ---------------------------------------------------------------------------
extern "C" void kernel_launch(void* const* d_in, const int* in_sizes, int n_in,
                              void* d_out, int out_size)
{
    const float* x    = (const float*)d_in[0];
    const float* h0   = (const float*)d_in[1];
    const float* w_ih = (const float*)d_in[2];
    const float* w_hh = (const float*)d_in[3];
    const float* b_ih = (const float*)d_in[4];
    const float* b_hh = (const float*)d_in[5];
    const float* w1   = (const float*)d_in[6];
    const float* b1   = (const float*)d_in[7];
    const float* w2   = (const float*)d_in[8];
    const float* b2   = (const float*)d_in[9];
    const float* w3   = (const float*)d_in[10];
    const float* b3   = (const float*)d_in[11];
    float* out = (float*)d_out;

    cudaFuncSetAttribute(fused_persist,
                         cudaFuncAttributeMaxDynamicSharedMemorySize, FUSED_SMEM);

    fused_persist<<<GRID_P, 512, FUSED_SMEM>>>(h0, x, w_ih, w_hh, b_ih, b_hh,
                                               w1, b1, w2, b2, w3, b3, out);
}